// round 9
// baseline (speedup 1.0000x reference)
#include <cuda_runtime.h>
#include <cuda_fp16.h>
#include <cstdint>

#define B_    4
#define N_    2048
#define DIM_  1536
#define H_    16
#define DH_   96
#define QKV3  4608      // 3*H*DH
#define HDH   1536      // H*DH
#define M_    (B_*N_)   // 8192
#define SCALE_ 0.10206207261596575f  // 96^-0.5

// ---------------- scratch (no allocations allowed) ----------------
__device__ __half g_xhi[(size_t)M_ * DIM_];
__device__ __half g_xlo[(size_t)M_ * DIM_];
__device__ __half g_chi[(size_t)M_ * HDH];
__device__ __half g_clo[(size_t)M_ * HDH];
__device__ __half g_wqt[(size_t)QKV3 * DIM_];        // W^T [N,K] single fp16
__device__ __half g_wot[(size_t)HDH * HDH];

// q hi/lo; k, v single fp16. layout [b*H + h][n][d]; q pre-scaled
#define PER_T ((size_t)B_ * H_ * N_ * DH_)
__device__ __half g_qh[PER_T];
__device__ __half g_ql[PER_T];
__device__ __half g_kk[PER_T];
__device__ __half g_vv[PER_T];

// cos/sin table: [chunk(3)][n(2048)][j(32)] -> (cos f, sin f)
__device__ float2 g_cs[3 * N_ * 32];

// ================= helpers (sm_80+ only) ==========================
__device__ __forceinline__ uint32_t smem_u32(const void* p) {
    uint32_t a;
    asm("{ .reg .u64 t; cvta.to.shared.u64 t, %1; cvt.u32.u64 %0, t; }"
        : "=r"(a) : "l"(p));
    return a;
}
#define CP_ASYNC16(saddr, gptr) \
    asm volatile("cp.async.cg.shared.global [%0], [%1], 16;" :: "r"(saddr), "l"(gptr))
#define CP_COMMIT() asm volatile("cp.async.commit_group;" ::: "memory")
#define CP_WAIT(n)  asm volatile("cp.async.wait_group %0;" :: "n"(n) : "memory")

#define LDMX4(r0,r1,r2,r3,addr) \
    asm volatile("ldmatrix.sync.aligned.m8n8.x4.shared.b16 {%0,%1,%2,%3}, [%4];" \
        : "=r"(r0),"=r"(r1),"=r"(r2),"=r"(r3) : "r"(addr))
#define LDMX4T(r0,r1,r2,r3,addr) \
    asm volatile("ldmatrix.sync.aligned.m8n8.x4.trans.shared.b16 {%0,%1,%2,%3}, [%4];" \
        : "=r"(r0),"=r"(r1),"=r"(r2),"=r"(r3) : "r"(addr))

__device__ __forceinline__ void mma_f16(float* c, const uint32_t* a, const uint32_t* b) {
    asm volatile(
        "mma.sync.aligned.m16n8k16.row.col.f32.f16.f16.f32 "
        "{%0,%1,%2,%3}, {%4,%5,%6,%7}, {%8,%9}, {%0,%1,%2,%3};"
        : "+f"(c[0]), "+f"(c[1]), "+f"(c[2]), "+f"(c[3])
        : "r"(a[0]), "r"(a[1]), "r"(a[2]), "r"(a[3]), "r"(b[0]), "r"(b[1]));
}
__device__ __forceinline__ uint32_t pk_h2(float a, float b) {
    __half2 t = __floats2half2_rn(a, b);
    return *(uint32_t*)&t;
}

// ---- cos/sin table init --------------------------------------------
__global__ void cs_init(const float* __restrict__ f1, const float* __restrict__ f2,
                        const float* __restrict__ f3) {
    const int i = blockIdx.x * 256 + threadIdx.x;
    if (i >= 3 * N_ * 32) return;
    const int chunk = i / (N_ * 32);
    const int rem = i - chunk * (N_ * 32);
    const float* f = (chunk == 0) ? f1 : ((chunk == 1) ? f2 : f3);
    const float fr = f[rem];
    g_cs[i] = make_float2(cosf(fr), sinf(fr));
}

// ====== 2-term fp16 mma.sync GEMM, 3-stage pipeline ===============
// ROPE=0: C = (Ah+Al)@Wt^T + bias (fp32 out).
// ROPE=1: QKV gemm; epilogue applies RoPE + head transpose, writes
//         g_qh/g_ql (scaled), g_kk, g_vv fp16 directly.
#define GS_STRIDE 80
#define GS_TILE   10240
#define GS_STAGE  30720
#define GEMM_SMEM (3 * GS_STAGE)    // 92160 B; 2 CTAs/SM = 184 KB

template <int ROPE>
__global__ void __launch_bounds__(256, 2)
gemm_mma(const __half* __restrict__ Ahi, const __half* __restrict__ Alo,
         const __half* __restrict__ Wt,
         const float* __restrict__ bias, float* __restrict__ C, int N, int K) {
    extern __shared__ char sm_[];
    const uint32_t sb = smem_u32(sm_);
    const int tid = threadIdx.x;
    const int wid = tid >> 5, lane = tid & 31;
    const int g = lane >> 2, tg = lane & 3;
    const int wm = wid & 3, wn = wid >> 2;
    const int brow = blockIdx.y * 128;
    const int bcol = blockIdx.x * 128;

    const int lane7 = lane & 7, sel = lane >> 3;
    const uint32_t a_rowadd = (uint32_t)(lane7 + ((sel & 1) ? 8 : 0));
    const uint32_t a_colb   = (uint32_t)(((sel >> 1) ? 8 : 0) * 2);
    const uint32_t b_rowadd = (uint32_t)(lane7 + ((sel & 2) ? 8 : 0));
    const uint32_t b_colb   = (uint32_t)(((sel & 1) ? 8 : 0) * 2);

    float acc[2][8][4];
#pragma unroll
    for (int mt = 0; mt < 2; mt++)
#pragma unroll
        for (int nt = 0; nt < 8; nt++)
#pragma unroll
            for (int i = 0; i < 4; i++) acc[mt][nt][i] = 0.f;

    const int nst = K / 32;

    auto load_stage = [&](int s, int buf) {
        const uint32_t base = sb + (uint32_t)buf * GS_STAGE;
        const int k0 = s * 32;
#pragma unroll
        for (int i = 0; i < 6; i++) {
            const int idx = tid + i * 256;
            const int tile = idx >> 9;
            const int w = idx & 511;
            const int r = w >> 2, c = w & 3;
            const uint32_t so = base + (uint32_t)tile * GS_TILE +
                                (uint32_t)r * GS_STRIDE + (uint32_t)c * 16;
            const char* gp;
            if (tile == 0)      gp = (const char*)Ahi + ((size_t)(brow + r) * K + k0 + c * 8) * 2;
            else if (tile == 1) gp = (const char*)Alo + ((size_t)(brow + r) * K + k0 + c * 8) * 2;
            else                gp = (const char*)Wt  + ((size_t)(bcol + r) * K + k0 + c * 8) * 2;
            CP_ASYNC16(so, gp);
        }
    };

    load_stage(0, 0); CP_COMMIT();
    load_stage(1, 1); CP_COMMIT();

    int buf = 0;                          // buffer holding stage s
    for (int s = 0; s < nst; s++) {
        if (s + 2 < nst) { CP_WAIT(1); }  // stage s arrived; s+1 may be in flight
        else             { CP_WAIT(0); }
        __syncthreads();                  // (a) data visible; (b) buf for s+2 free
        if (s + 2 < nst) {
            int nb = buf + 2; if (nb >= 3) nb -= 3;
            load_stage(s + 2, nb);
            CP_COMMIT();
        }

        const uint32_t base = sb + (uint32_t)buf * GS_STAGE;
#pragma unroll
        for (int kk = 0; kk < 2; kk++) {
            const uint32_t kb = (uint32_t)(kk * 16) * 2;
            uint32_t ah[2][4], al[2][4], bw[8][2];
#pragma unroll
            for (int mt = 0; mt < 2; mt++) {
                const uint32_t ar = base + (uint32_t)(wm * 32 + mt * 16 + a_rowadd) * GS_STRIDE
                                  + kb + a_colb;
                LDMX4(ah[mt][0], ah[mt][1], ah[mt][2], ah[mt][3], ar);
                LDMX4(al[mt][0], al[mt][1], al[mt][2], al[mt][3], ar + GS_TILE);
            }
#pragma unroll
            for (int nb2 = 0; nb2 < 4; nb2++) {
                const uint32_t br = base + 2 * GS_TILE
                                  + (uint32_t)(wn * 64 + nb2 * 16 + b_rowadd) * GS_STRIDE
                                  + kb + b_colb;
                LDMX4(bw[2*nb2][0], bw[2*nb2][1], bw[2*nb2+1][0], bw[2*nb2+1][1], br);
            }
#pragma unroll
            for (int mt = 0; mt < 2; mt++)
#pragma unroll
                for (int nt = 0; nt < 8; nt++) {
                    mma_f16(acc[mt][nt], ah[mt], bw[nt]);
                    mma_f16(acc[mt][nt], al[mt], bw[nt]);
                }
        }
        if (++buf >= 3) buf -= 3;
    }

    if (ROPE) {
        const int which = bcol / HDH;   // 0=q 1=k 2=v
#pragma unroll
        for (int mt = 0; mt < 2; mt++) {
#pragma unroll
            for (int hf = 0; hf < 2; hf++) {
                const int row = brow + wm * 32 + mt * 16 + g + hf * 8;
                const int bb = row >> 11, n = row & (N_ - 1);
                const int i0 = hf * 2;
#pragma unroll
                for (int pp = 0; pp < 4; pp++) {
                    const int ntA = (pp >> 1) * 4 + (pp & 1);
                    const int ntB = ntA + 2;
                    const int cA = bcol + wn * 64 + ntA * 8 + tg * 2;
                    const int cq = cA - which * HDH;
                    const int hh = cq / DH_;
                    const int dA = cq - hh * DH_;
                    const int jA = dA & 31;
                    const int chunk = dA >> 5;
                    const float a0 = acc[mt][ntA][i0], a1 = acc[mt][ntA][i0 + 1];
                    const float b0 = acc[mt][ntB][i0], b1 = acc[mt][ntB][i0 + 1];
                    float oA0, oA1, oB0, oB1;
                    if (which == 2) {
                        oA0 = a0; oA1 = a1; oB0 = b0; oB1 = b1;
                    } else {
                        const float2* csp = g_cs + (size_t)(chunk * N_ + n) * 32;
                        const float2 cA0 = csp[jA],      cA1 = csp[jA + 1];
                        const float2 cB0 = csp[jA + 16], cB1 = csp[jA + 17];
                        oA0 = a0 * cA0.x - b0 * cA0.y;
                        oA1 = a1 * cA1.x - b1 * cA1.y;
                        oB0 = b0 * cB0.x + a0 * cB0.y;
                        oB1 = b1 * cB1.x + a1 * cB1.y;
                        if (which == 0) {
                            oA0 *= SCALE_; oA1 *= SCALE_; oB0 *= SCALE_; oB1 *= SCALE_;
                        }
                    }
                    const size_t oA = ((size_t)((bb * H_ + hh) * N_ + n)) * DH_ + dA;
                    const size_t oB = oA + 16;
                    if (which == 0) {
                        const __half hA0 = __float2half(oA0), hA1 = __float2half(oA1);
                        const __half hB0 = __float2half(oB0), hB1 = __float2half(oB1);
                        *(__half2*)(g_qh + oA) = __halves2half2(hA0, hA1);
                        *(__half2*)(g_ql + oA) =
                            __floats2half2_rn(oA0 - __half2float(hA0), oA1 - __half2float(hA1));
                        *(__half2*)(g_qh + oB) = __halves2half2(hB0, hB1);
                        *(__half2*)(g_ql + oB) =
                            __floats2half2_rn(oB0 - __half2float(hB0), oB1 - __half2float(hB1));
                    } else if (which == 1) {
                        *(__half2*)(g_kk + oA) = __floats2half2_rn(oA0, oA1);
                        *(__half2*)(g_kk + oB) = __floats2half2_rn(oB0, oB1);
                    } else {
                        *(__half2*)(g_vv + oA) = __floats2half2_rn(oA0, oA1);
                        *(__half2*)(g_vv + oB) = __floats2half2_rn(oB0, oB1);
                    }
                }
            }
        }
    } else {
#pragma unroll
        for (int mt = 0; mt < 2; mt++) {
            const int r0 = brow + wm * 32 + mt * 16 + g;
#pragma unroll
            for (int nt = 0; nt < 8; nt++) {
                const int c = bcol + wn * 64 + nt * 8 + tg * 2;
                float2 v0 = make_float2(acc[mt][nt][0], acc[mt][nt][1]);
                float2 v1 = make_float2(acc[mt][nt][2], acc[mt][nt][3]);
                const float b0 = bias[c], b1 = bias[c + 1];
                v0.x += b0; v0.y += b1; v1.x += b0; v1.y += b1;
                *(float2*)(C + (size_t)r0 * N + c)       = v0;
                *(float2*)(C + (size_t)(r0 + 8) * N + c) = v1;
            }
        }
    }
}

// ---------------- fp32 -> fp16 hi/lo ------------------------------
__global__ void cvt_hilo(const float* __restrict__ src,
                         __half* __restrict__ hi, __half* __restrict__ lo, int n4) {
    const int i = blockIdx.x * blockDim.x + threadIdx.x;
    if (i >= n4) return;
    const float4 v = ((const float4*)src)[i];
    const __half h0 = __float2half(v.x), h1 = __float2half(v.y);
    const __half h2 = __float2half(v.z), h3 = __float2half(v.w);
    ((__half2*)hi)[i * 2]     = __halves2half2(h0, h1);
    ((__half2*)hi)[i * 2 + 1] = __halves2half2(h2, h3);
    ((__half2*)lo)[i * 2]     = __floats2half2_rn(v.x - __half2float(h0), v.y - __half2float(h1));
    ((__half2*)lo)[i * 2 + 1] = __floats2half2_rn(v.z - __half2float(h2), v.w - __half2float(h3));
}

// W [K,N] -> W^T [N,K] single fp16
__global__ void transpose_f16(const float* __restrict__ W,
                              __half* __restrict__ Wt, int K, int N) {
    __shared__ float t[32][33];
    const int n0 = blockIdx.x * 32, k0 = blockIdx.y * 32;
    const int tx = threadIdx.x;
    for (int y = threadIdx.y; y < 32; y += 8)
        t[y][tx] = W[(size_t)(k0 + y) * N + n0 + tx];
    __syncthreads();
    for (int y = threadIdx.y; y < 32; y += 8)
        Wt[(size_t)(n0 + y) * K + k0 + tx] = __float2half(t[tx][y]);
}

// ---------------- Flash attention (fp16 2-term mma.sync) ----------
#define FBM    128
#define FBN    64
#define FSTRIDE 208
#define FTILE  (64 * FSTRIDE)
#define FSTAGE (2 * FTILE)
#define FLASH_SMEM (2 * FSTAGE)

__global__ void __launch_bounds__(256, 1) flash_mma() {
    extern __shared__ char sm_[];
    const uint32_t sb = smem_u32(sm_);
    const int tid = threadIdx.x;
    const int wid = tid >> 5, lane = tid & 31;
    const int g = lane >> 2, tg = lane & 3;
    const int bh = blockIdx.y;
    const int b  = bh >> 4, h = bh & 15;
    const int m0 = blockIdx.x * FBM;

    const size_t tbase = (size_t)bh * N_ * DH_;

    const int qrow = m0 + wid * 16 + g;
    const char* qh = (const char*)(g_qh + tbase + (size_t)qrow * DH_);
    const char* ql = (const char*)(g_ql + tbase + (size_t)qrow * DH_);
    uint32_t qa_h[6][4], qa_l[6][4];
#pragma unroll
    for (int j = 0; j < 6; j++) {
        const int c0 = (j * 16 + tg * 2) * 2;
        qa_h[j][0] = *(const uint32_t*)(qh + c0);
        qa_h[j][1] = *(const uint32_t*)(qh + 8 * DH_ * 2 + c0);
        qa_h[j][2] = *(const uint32_t*)(qh + c0 + 16);
        qa_h[j][3] = *(const uint32_t*)(qh + 8 * DH_ * 2 + c0 + 16);
        qa_l[j][0] = *(const uint32_t*)(ql + c0);
        qa_l[j][1] = *(const uint32_t*)(ql + 8 * DH_ * 2 + c0);
        qa_l[j][2] = *(const uint32_t*)(ql + c0 + 16);
        qa_l[j][3] = *(const uint32_t*)(ql + 8 * DH_ * 2 + c0 + 16);
    }

    float oacc[12][4];
#pragma unroll
    for (int ot = 0; ot < 12; ot++)
#pragma unroll
        for (int i = 0; i < 4; i++) oacc[ot][i] = 0.f;
    float mrow0 = -1e30f, mrow1 = -1e30f, lrow0 = 0.f, lrow1 = 0.f;

    const char* srcK = (const char*)(g_kk + tbase);
    const char* srcV = (const char*)(g_vv + tbase);

    auto load_stage = [&](int s) {
        const uint32_t base = sb + (uint32_t)(s & 1) * FSTAGE;
        const int n0 = s * FBN;
#pragma unroll
        for (int i = 0; i < 6; i++) {
            const int idx = tid + i * 256;
            const int tile = idx / 768;
            const int w = idx % 768;
            const int r = w / 12, c = w % 12;
            const uint32_t so = base + (uint32_t)tile * FTILE +
                                (uint32_t)r * FSTRIDE + (uint32_t)c * 16;
            const size_t go = ((size_t)(n0 + r) * DH_ + c * 8) * 2;
            CP_ASYNC16(so, (tile == 0 ? srcK : srcV) + go);
        }
    };

    load_stage(0); CP_COMMIT();

    const int nkv = N_ / FBN;
    for (int s = 0; s < nkv; s++) {
        if (s + 1 < nkv) { load_stage(s + 1); CP_COMMIT(); CP_WAIT(1); }
        else             { CP_WAIT(0); }
        __syncthreads();

        const uint32_t kb = sb + (uint32_t)(s & 1) * FSTAGE;
        const uint32_t vb = kb + FTILE;

        float sacc[8][4];
#pragma unroll
        for (int nt = 0; nt < 8; nt++)
#pragma unroll
            for (int i = 0; i < 4; i++) sacc[nt][i] = 0.f;

#pragma unroll
        for (int j = 0; j < 6; j++) {
            uint32_t bf[8][2];
#pragma unroll
            for (int np = 0; np < 4; np++) {
                const int sel = lane >> 3;
                const uint32_t row = (uint32_t)(np * 16 + ((sel & 2) ? 8 : 0) + (lane & 7));
                const uint32_t col = (uint32_t)(j * 16 + ((sel & 1) ? 8 : 0));
                const uint32_t ad = kb + row * FSTRIDE + col * 2;
                LDMX4(bf[2*np][0], bf[2*np][1], bf[2*np+1][0], bf[2*np+1][1], ad);
            }
#pragma unroll
            for (int nt = 0; nt < 8; nt++) {
                mma_f16(sacc[nt], qa_h[j], bf[nt]);
                mma_f16(sacc[nt], qa_l[j], bf[nt]);
            }
        }

        float mx0 = -1e30f, mx1 = -1e30f;
#pragma unroll
        for (int nt = 0; nt < 8; nt++) {
            mx0 = fmaxf(mx0, fmaxf(sacc[nt][0], sacc[nt][1]));
            mx1 = fmaxf(mx1, fmaxf(sacc[nt][2], sacc[nt][3]));
        }
        mx0 = fmaxf(mx0, __shfl_xor_sync(0xffffffffu, mx0, 1));
        mx0 = fmaxf(mx0, __shfl_xor_sync(0xffffffffu, mx0, 2));
        mx1 = fmaxf(mx1, __shfl_xor_sync(0xffffffffu, mx1, 1));
        mx1 = fmaxf(mx1, __shfl_xor_sync(0xffffffffu, mx1, 2));

        const float mn0 = fmaxf(mrow0, mx0), mn1 = fmaxf(mrow1, mx1);
        const float corr0 = __expf(mrow0 - mn0), corr1 = __expf(mrow1 - mn1);
        mrow0 = mn0; mrow1 = mn1;

        float sum0 = 0.f, sum1 = 0.f;
#pragma unroll
        for (int nt = 0; nt < 8; nt++) {
            sacc[nt][0] = __expf(sacc[nt][0] - mn0);
            sacc[nt][1] = __expf(sacc[nt][1] - mn0);
            sacc[nt][2] = __expf(sacc[nt][2] - mn1);
            sacc[nt][3] = __expf(sacc[nt][3] - mn1);
            sum0 += sacc[nt][0] + sacc[nt][1];
            sum1 += sacc[nt][2] + sacc[nt][3];
        }
        lrow0 = lrow0 * corr0 + sum0;
        lrow1 = lrow1 * corr1 + sum1;
#pragma unroll
        for (int ot = 0; ot < 12; ot++) {
            oacc[ot][0] *= corr0; oacc[ot][1] *= corr0;
            oacc[ot][2] *= corr1; oacc[ot][3] *= corr1;
        }

#pragma unroll
        for (int jj = 0; jj < 4; jj++) {
            uint32_t pa_h[4], pa_l[4];
            {
                const float p00 = sacc[2*jj][0],   p01 = sacc[2*jj][1];
                const float p10 = sacc[2*jj][2],   p11 = sacc[2*jj][3];
                const float p20 = sacc[2*jj+1][0], p21 = sacc[2*jj+1][1];
                const float p30 = sacc[2*jj+1][2], p31 = sacc[2*jj+1][3];
                pa_h[0] = pk_h2(p00, p01);
                pa_h[1] = pk_h2(p10, p11);
                pa_h[2] = pk_h2(p20, p21);
                pa_h[3] = pk_h2(p30, p31);
                pa_l[0] = pk_h2(p00 - __half2float(__float2half(p00)),
                                p01 - __half2float(__float2half(p01)));
                pa_l[1] = pk_h2(p10 - __half2float(__float2half(p10)),
                                p11 - __half2float(__float2half(p11)));
                pa_l[2] = pk_h2(p20 - __half2float(__float2half(p20)),
                                p21 - __half2float(__float2half(p21)));
                pa_l[3] = pk_h2(p30 - __half2float(__float2half(p30)),
                                p31 - __half2float(__float2half(p31)));
            }
#pragma unroll
            for (int np = 0; np < 6; np++) {
                uint32_t vf[2][2];
                const int sel = lane >> 3;
                const uint32_t row = (uint32_t)(jj * 16 + ((sel & 1) ? 8 : 0) + (lane & 7));
                const uint32_t col = (uint32_t)(np * 16 + ((sel & 2) ? 8 : 0));
                const uint32_t ad = vb + row * FSTRIDE + col * 2;
                LDMX4T(vf[0][0], vf[0][1], vf[1][0], vf[1][1], ad);
                mma_f16(oacc[2*np],   pa_h, vf[0]);
                mma_f16(oacc[2*np],   pa_l, vf[0]);
                mma_f16(oacc[2*np+1], pa_h, vf[1]);
                mma_f16(oacc[2*np+1], pa_l, vf[1]);
            }
        }
        __syncthreads();
    }

    lrow0 += __shfl_xor_sync(0xffffffffu, lrow0, 1);
    lrow0 += __shfl_xor_sync(0xffffffffu, lrow0, 2);
    lrow1 += __shfl_xor_sync(0xffffffffu, lrow1, 1);
    lrow1 += __shfl_xor_sync(0xffffffffu, lrow1, 2);
    const float inv0 = 1.f / lrow0, inv1 = 1.f / lrow1;

    const int nrow = m0 + wid * 16 + g;
    const size_t ob0 = (size_t)(b * N_ + nrow) * HDH + h * DH_;
    const size_t ob1 = (size_t)(b * N_ + nrow + 8) * HDH + h * DH_;
#pragma unroll
    for (int ot = 0; ot < 12; ot++) {
        const int d0 = ot * 8 + tg * 2;
        const float f00 = oacc[ot][0] * inv0, f01 = oacc[ot][1] * inv0;
        const float f10 = oacc[ot][2] * inv1, f11 = oacc[ot][3] * inv1;
        const __half h00 = __float2half(f00), h01 = __float2half(f01);
        const __half h10 = __float2half(f10), h11 = __float2half(f11);
        *(__half2*)(g_chi + ob0 + d0) = __halves2half2(h00, h01);
        *(__half2*)(g_clo + ob0 + d0) =
            __floats2half2_rn(f00 - __half2float(h00), f01 - __half2float(h01));
        *(__half2*)(g_chi + ob1 + d0) = __halves2half2(h10, h11);
        *(__half2*)(g_clo + ob1 + d0) =
            __floats2half2_rn(f10 - __half2float(h10), f11 - __half2float(h11));
    }
}

// ------------------------------------------------------------------
extern "C" void kernel_launch(void* const* d_in, const int* in_sizes, int n_in,
                              void* d_out, int out_size) {
    const float* x    = (const float*)d_in[0];
    const float* f1   = (const float*)d_in[1];
    const float* f2   = (const float*)d_in[2];
    const float* f3   = (const float*)d_in[3];
    const float* Wqkv = (const float*)d_in[4];
    const float* Wout = (const float*)d_in[5];
    const float* bout = (const float*)d_in[6];
    float* out = (float*)d_out;

    __half *xhi, *xlo, *chi, *clo, *wqt, *wot;
    cudaGetSymbolAddress((void**)&xhi, g_xhi);
    cudaGetSymbolAddress((void**)&xlo, g_xlo);
    cudaGetSymbolAddress((void**)&chi, g_chi);
    cudaGetSymbolAddress((void**)&clo, g_clo);
    cudaGetSymbolAddress((void**)&wqt, g_wqt);
    cudaGetSymbolAddress((void**)&wot, g_wot);

    cudaFuncSetAttribute(gemm_mma<0>, cudaFuncAttributeMaxDynamicSharedMemorySize, GEMM_SMEM);
    cudaFuncSetAttribute(gemm_mma<1>, cudaFuncAttributeMaxDynamicSharedMemorySize, GEMM_SMEM);
    cudaFuncSetAttribute(flash_mma, cudaFuncAttributeMaxDynamicSharedMemorySize, FLASH_SMEM);

    // 0) cos/sin table
    cs_init<<<(3 * N_ * 32 + 255) / 256, 256>>>(f1, f2, f3);

    // 1) x -> fp16 hi/lo; weights -> transposed fp16
    cvt_hilo<<<(M_ * DIM_ / 4 + 255) / 256, 256>>>(x, xhi, xlo, M_ * DIM_ / 4);
    transpose_f16<<<dim3(QKV3 / 32, DIM_ / 32), dim3(32, 8)>>>(Wqkv, wqt, DIM_, QKV3);
    transpose_f16<<<dim3(HDH / 32, HDH / 32), dim3(32, 8)>>>(Wout, wot, HDH, HDH);

    // 2) QKV GEMM with fused RoPE + head-transpose epilogue
    gemm_mma<1><<<dim3(QKV3 / 128, M_ / 128), 256, GEMM_SMEM>>>(
        xhi, xlo, wqt, nullptr, nullptr, QKV3, DIM_);

    // 3) Flash attention (writes ctx hi/lo fp16 directly)
    flash_mma<<<dim3(N_ / FBM, B_ * H_), 256, FLASH_SMEM>>>();

    // 4) Output GEMM + bias
    gemm_mma<0><<<dim3(HDH / 128, M_ / 128), 256, GEMM_SMEM>>>(
        chi, clo, wot, bout, out, HDH, HDH);
}

// round 10
// speedup vs baseline: 1.0881x; 1.0881x over previous
#include <cuda_runtime.h>
#include <cuda_fp16.h>
#include <cstdint>

#define B_    4
#define N_    2048
#define DIM_  1536
#define H_    16
#define DH_   96
#define QKV3  4608      // 3*H*DH
#define HDH   1536      // H*DH
#define M_    (B_*N_)   // 8192
#define SCALE_ 0.10206207261596575f  // 96^-0.5

// ---------------- scratch (no allocations allowed) ----------------
__device__ __half g_xhi[(size_t)M_ * DIM_];
__device__ __half g_xlo[(size_t)M_ * DIM_];
__device__ __half g_chi[(size_t)M_ * HDH];
__device__ __half g_clo[(size_t)M_ * HDH];
__device__ __half g_wqt[(size_t)QKV3 * DIM_];        // W^T [N,K] single fp16
__device__ __half g_wot[(size_t)HDH * HDH];

// q hi/lo; k, v single fp16. layout [b*H + h][n][d]; q pre-scaled
#define PER_T ((size_t)B_ * H_ * N_ * DH_)
__device__ __half g_qh[PER_T];
__device__ __half g_ql[PER_T];
__device__ __half g_kk[PER_T];
__device__ __half g_vv[PER_T];

// cos/sin table: [chunk(3)][n(2048)][j(32)] -> (cos f, sin f)
__device__ float2 g_cs[3 * N_ * 32];

// ================= helpers (sm_80+ only) ==========================
__device__ __forceinline__ uint32_t smem_u32(const void* p) {
    uint32_t a;
    asm("{ .reg .u64 t; cvta.to.shared.u64 t, %1; cvt.u32.u64 %0, t; }"
        : "=r"(a) : "l"(p));
    return a;
}
#define CP_ASYNC16(saddr, gptr) \
    asm volatile("cp.async.cg.shared.global [%0], [%1], 16;" :: "r"(saddr), "l"(gptr))
#define CP_COMMIT() asm volatile("cp.async.commit_group;" ::: "memory")
#define CP_WAIT(n)  asm volatile("cp.async.wait_group %0;" :: "n"(n) : "memory")

#define LDMX4(r0,r1,r2,r3,addr) \
    asm volatile("ldmatrix.sync.aligned.m8n8.x4.shared.b16 {%0,%1,%2,%3}, [%4];" \
        : "=r"(r0),"=r"(r1),"=r"(r2),"=r"(r3) : "r"(addr))
#define LDMX4T(r0,r1,r2,r3,addr) \
    asm volatile("ldmatrix.sync.aligned.m8n8.x4.trans.shared.b16 {%0,%1,%2,%3}, [%4];" \
        : "=r"(r0),"=r"(r1),"=r"(r2),"=r"(r3) : "r"(addr))

__device__ __forceinline__ void mma_f16(float* c, const uint32_t* a, const uint32_t* b) {
    asm volatile(
        "mma.sync.aligned.m16n8k16.row.col.f32.f16.f16.f32 "
        "{%0,%1,%2,%3}, {%4,%5,%6,%7}, {%8,%9}, {%0,%1,%2,%3};"
        : "+f"(c[0]), "+f"(c[1]), "+f"(c[2]), "+f"(c[3])
        : "r"(a[0]), "r"(a[1]), "r"(a[2]), "r"(a[3]), "r"(b[0]), "r"(b[1]));
}
__device__ __forceinline__ uint32_t pk_h2(float a, float b) {
    __half2 t = __floats2half2_rn(a, b);
    return *(uint32_t*)&t;
}

// ---- cos/sin table init --------------------------------------------
__global__ void cs_init(const float* __restrict__ f1, const float* __restrict__ f2,
                        const float* __restrict__ f3) {
    const int i = blockIdx.x * 256 + threadIdx.x;
    if (i >= 3 * N_ * 32) return;
    const int chunk = i / (N_ * 32);
    const int rem = i - chunk * (N_ * 32);
    const float* f = (chunk == 0) ? f1 : ((chunk == 1) ? f2 : f3);
    const float fr = f[rem];
    g_cs[i] = make_float2(cosf(fr), sinf(fr));
}

// ====== 2-term fp16 mma.sync GEMM (R8 2-stage pipeline) ===========
// ROPE=0: C = (Ah+Al)@Wt^T + bias (fp32 out).
// ROPE=1: QKV gemm; epilogue applies RoPE + head transpose, writes
//         g_qh/g_ql (scaled), g_kk, g_vv fp16 directly.
#define GS_STRIDE 80
#define GS_TILE   10240
#define GS_STAGE  30720
#define GEMM_SMEM (2 * GS_STAGE)

template <int ROPE>
__global__ void __launch_bounds__(256, 2)
gemm_mma(const __half* __restrict__ Ahi, const __half* __restrict__ Alo,
         const __half* __restrict__ Wt,
         const float* __restrict__ bias, float* __restrict__ C, int N, int K) {
    extern __shared__ char sm_[];
    const uint32_t sb = smem_u32(sm_);
    const int tid = threadIdx.x;
    const int wid = tid >> 5, lane = tid & 31;
    const int g = lane >> 2, tg = lane & 3;
    const int wm = wid & 3, wn = wid >> 2;
    const int brow = blockIdx.y * 128;
    const int bcol = blockIdx.x * 128;

    const int lane7 = lane & 7, sel = lane >> 3;
    const uint32_t a_rowadd = (uint32_t)(lane7 + ((sel & 1) ? 8 : 0));
    const uint32_t a_colb   = (uint32_t)(((sel >> 1) ? 8 : 0) * 2);
    const uint32_t b_rowadd = (uint32_t)(lane7 + ((sel & 2) ? 8 : 0));
    const uint32_t b_colb   = (uint32_t)(((sel & 1) ? 8 : 0) * 2);

    float acc[2][8][4];
#pragma unroll
    for (int mt = 0; mt < 2; mt++)
#pragma unroll
        for (int nt = 0; nt < 8; nt++)
#pragma unroll
            for (int i = 0; i < 4; i++) acc[mt][nt][i] = 0.f;

    const int nst = K / 32;

    auto load_stage = [&](int s) {
        const uint32_t base = sb + (uint32_t)(s & 1) * GS_STAGE;
        const int k0 = s * 32;
#pragma unroll
        for (int i = 0; i < 6; i++) {
            const int idx = tid + i * 256;
            const int tile = idx >> 9;
            const int w = idx & 511;
            const int r = w >> 2, c = w & 3;
            const uint32_t so = base + (uint32_t)tile * GS_TILE +
                                (uint32_t)r * GS_STRIDE + (uint32_t)c * 16;
            const char* gp;
            if (tile == 0)      gp = (const char*)Ahi + ((size_t)(brow + r) * K + k0 + c * 8) * 2;
            else if (tile == 1) gp = (const char*)Alo + ((size_t)(brow + r) * K + k0 + c * 8) * 2;
            else                gp = (const char*)Wt  + ((size_t)(bcol + r) * K + k0 + c * 8) * 2;
            CP_ASYNC16(so, gp);
        }
    };

    load_stage(0); CP_COMMIT();

    for (int s = 0; s < nst; s++) {
        if (s + 1 < nst) { load_stage(s + 1); CP_COMMIT(); CP_WAIT(1); }
        else             { CP_WAIT(0); }
        __syncthreads();

        const uint32_t base = sb + (uint32_t)(s & 1) * GS_STAGE;
#pragma unroll
        for (int kk = 0; kk < 2; kk++) {
            const uint32_t kb = (uint32_t)(kk * 16) * 2;
            uint32_t ah[2][4], al[2][4], bw[8][2];
#pragma unroll
            for (int mt = 0; mt < 2; mt++) {
                const uint32_t ar = base + (uint32_t)(wm * 32 + mt * 16 + a_rowadd) * GS_STRIDE
                                  + kb + a_colb;
                LDMX4(ah[mt][0], ah[mt][1], ah[mt][2], ah[mt][3], ar);
                LDMX4(al[mt][0], al[mt][1], al[mt][2], al[mt][3], ar + GS_TILE);
            }
#pragma unroll
            for (int nb = 0; nb < 4; nb++) {
                const uint32_t br = base + 2 * GS_TILE
                                  + (uint32_t)(wn * 64 + nb * 16 + b_rowadd) * GS_STRIDE
                                  + kb + b_colb;
                LDMX4(bw[2*nb][0], bw[2*nb][1], bw[2*nb+1][0], bw[2*nb+1][1], br);
            }
#pragma unroll
            for (int mt = 0; mt < 2; mt++)
#pragma unroll
                for (int nt = 0; nt < 8; nt++) {
                    mma_f16(acc[mt][nt], ah[mt], bw[nt]);
                    mma_f16(acc[mt][nt], al[mt], bw[nt]);
                }
        }
        __syncthreads();
    }

    if (ROPE) {
        const int which = bcol / HDH;   // 0=q 1=k 2=v
#pragma unroll
        for (int mt = 0; mt < 2; mt++) {
#pragma unroll
            for (int hf = 0; hf < 2; hf++) {
                const int row = brow + wm * 32 + mt * 16 + g + hf * 8;
                const int bb = row >> 11, n = row & (N_ - 1);
                const int i0 = hf * 2;
#pragma unroll
                for (int pp = 0; pp < 4; pp++) {
                    const int ntA = (pp >> 1) * 4 + (pp & 1);
                    const int ntB = ntA + 2;
                    const int cA = bcol + wn * 64 + ntA * 8 + tg * 2;
                    const int cq = cA - which * HDH;
                    const int hh = cq / DH_;
                    const int dA = cq - hh * DH_;
                    const int jA = dA & 31;
                    const int chunk = dA >> 5;
                    const float a0 = acc[mt][ntA][i0], a1 = acc[mt][ntA][i0 + 1];
                    const float b0 = acc[mt][ntB][i0], b1 = acc[mt][ntB][i0 + 1];
                    float oA0, oA1, oB0, oB1;
                    if (which == 2) {
                        oA0 = a0; oA1 = a1; oB0 = b0; oB1 = b1;
                    } else {
                        const float2* csp = g_cs + (size_t)(chunk * N_ + n) * 32;
                        const float2 cA0 = csp[jA],      cA1 = csp[jA + 1];
                        const float2 cB0 = csp[jA + 16], cB1 = csp[jA + 17];
                        oA0 = a0 * cA0.x - b0 * cA0.y;
                        oA1 = a1 * cA1.x - b1 * cA1.y;
                        oB0 = b0 * cB0.x + a0 * cB0.y;
                        oB1 = b1 * cB1.x + a1 * cB1.y;
                        if (which == 0) {
                            oA0 *= SCALE_; oA1 *= SCALE_; oB0 *= SCALE_; oB1 *= SCALE_;
                        }
                    }
                    const size_t oA = ((size_t)((bb * H_ + hh) * N_ + n)) * DH_ + dA;
                    const size_t oB = oA + 16;
                    if (which == 0) {
                        const __half hA0 = __float2half(oA0), hA1 = __float2half(oA1);
                        const __half hB0 = __float2half(oB0), hB1 = __float2half(oB1);
                        *(__half2*)(g_qh + oA) = __halves2half2(hA0, hA1);
                        *(__half2*)(g_ql + oA) =
                            __floats2half2_rn(oA0 - __half2float(hA0), oA1 - __half2float(hA1));
                        *(__half2*)(g_qh + oB) = __halves2half2(hB0, hB1);
                        *(__half2*)(g_ql + oB) =
                            __floats2half2_rn(oB0 - __half2float(hB0), oB1 - __half2float(hB1));
                    } else if (which == 1) {
                        *(__half2*)(g_kk + oA) = __floats2half2_rn(oA0, oA1);
                        *(__half2*)(g_kk + oB) = __floats2half2_rn(oB0, oB1);
                    } else {
                        *(__half2*)(g_vv + oA) = __floats2half2_rn(oA0, oA1);
                        *(__half2*)(g_vv + oB) = __floats2half2_rn(oB0, oB1);
                    }
                }
            }
        }
    } else {
#pragma unroll
        for (int mt = 0; mt < 2; mt++) {
            const int r0 = brow + wm * 32 + mt * 16 + g;
#pragma unroll
            for (int nt = 0; nt < 8; nt++) {
                const int c = bcol + wn * 64 + nt * 8 + tg * 2;
                float2 v0 = make_float2(acc[mt][nt][0], acc[mt][nt][1]);
                float2 v1 = make_float2(acc[mt][nt][2], acc[mt][nt][3]);
                const float b0 = bias[c], b1 = bias[c + 1];
                v0.x += b0; v0.y += b1; v1.x += b0; v1.y += b1;
                *(float2*)(C + (size_t)r0 * N + c)       = v0;
                *(float2*)(C + (size_t)(r0 + 8) * N + c) = v1;
            }
        }
    }
}

// ---------------- fp32 -> fp16 hi/lo ------------------------------
__global__ void cvt_hilo(const float* __restrict__ src,
                         __half* __restrict__ hi, __half* __restrict__ lo, int n4) {
    const int i = blockIdx.x * blockDim.x + threadIdx.x;
    if (i >= n4) return;
    const float4 v = ((const float4*)src)[i];
    const __half h0 = __float2half(v.x), h1 = __float2half(v.y);
    const __half h2 = __float2half(v.z), h3 = __float2half(v.w);
    ((__half2*)hi)[i * 2]     = __halves2half2(h0, h1);
    ((__half2*)hi)[i * 2 + 1] = __halves2half2(h2, h3);
    ((__half2*)lo)[i * 2]     = __floats2half2_rn(v.x - __half2float(h0), v.y - __half2float(h1));
    ((__half2*)lo)[i * 2 + 1] = __floats2half2_rn(v.z - __half2float(h2), v.w - __half2float(h3));
}

// W [K,N] -> W^T [N,K] single fp16
__global__ void transpose_f16(const float* __restrict__ W,
                              __half* __restrict__ Wt, int K, int N) {
    __shared__ float t[32][33];
    const int n0 = blockIdx.x * 32, k0 = blockIdx.y * 32;
    const int tx = threadIdx.x;
    for (int y = threadIdx.y; y < 32; y += 8)
        t[y][tx] = W[(size_t)(k0 + y) * N + n0 + tx];
    __syncthreads();
    for (int y = threadIdx.y; y < 32; y += 8)
        Wt[(size_t)(n0 + y) * K + k0 + tx] = __float2half(t[tx][y]);
}

// ---------------- Flash attention (fp16 mma.sync) -----------------
// Q 2-term (hi/lo); K, V, P single fp16. Writes ctx hi/lo fp16.
#define FBM    128
#define FBN    64
#define FSTRIDE 208
#define FTILE  (64 * FSTRIDE)
#define FSTAGE (2 * FTILE)
#define FLASH_SMEM (2 * FSTAGE)

__global__ void __launch_bounds__(256, 1) flash_mma() {
    extern __shared__ char sm_[];
    const uint32_t sb = smem_u32(sm_);
    const int tid = threadIdx.x;
    const int wid = tid >> 5, lane = tid & 31;
    const int g = lane >> 2, tg = lane & 3;
    const int bh = blockIdx.y;
    const int b  = bh >> 4, h = bh & 15;
    const int m0 = blockIdx.x * FBM;

    const size_t tbase = (size_t)bh * N_ * DH_;

    const int qrow = m0 + wid * 16 + g;
    const char* qh = (const char*)(g_qh + tbase + (size_t)qrow * DH_);
    const char* ql = (const char*)(g_ql + tbase + (size_t)qrow * DH_);
    uint32_t qa_h[6][4], qa_l[6][4];
#pragma unroll
    for (int j = 0; j < 6; j++) {
        const int c0 = (j * 16 + tg * 2) * 2;
        qa_h[j][0] = *(const uint32_t*)(qh + c0);
        qa_h[j][1] = *(const uint32_t*)(qh + 8 * DH_ * 2 + c0);
        qa_h[j][2] = *(const uint32_t*)(qh + c0 + 16);
        qa_h[j][3] = *(const uint32_t*)(qh + 8 * DH_ * 2 + c0 + 16);
        qa_l[j][0] = *(const uint32_t*)(ql + c0);
        qa_l[j][1] = *(const uint32_t*)(ql + 8 * DH_ * 2 + c0);
        qa_l[j][2] = *(const uint32_t*)(ql + c0 + 16);
        qa_l[j][3] = *(const uint32_t*)(ql + 8 * DH_ * 2 + c0 + 16);
    }

    float oacc[12][4];
#pragma unroll
    for (int ot = 0; ot < 12; ot++)
#pragma unroll
        for (int i = 0; i < 4; i++) oacc[ot][i] = 0.f;
    float mrow0 = -1e30f, mrow1 = -1e30f, lrow0 = 0.f, lrow1 = 0.f;

    const char* srcK = (const char*)(g_kk + tbase);
    const char* srcV = (const char*)(g_vv + tbase);

    auto load_stage = [&](int s) {
        const uint32_t base = sb + (uint32_t)(s & 1) * FSTAGE;
        const int n0 = s * FBN;
#pragma unroll
        for (int i = 0; i < 6; i++) {
            const int idx = tid + i * 256;
            const int tile = idx / 768;
            const int w = idx % 768;
            const int r = w / 12, c = w % 12;
            const uint32_t so = base + (uint32_t)tile * FTILE +
                                (uint32_t)r * FSTRIDE + (uint32_t)c * 16;
            const size_t go = ((size_t)(n0 + r) * DH_ + c * 8) * 2;
            CP_ASYNC16(so, (tile == 0 ? srcK : srcV) + go);
        }
    };

    load_stage(0); CP_COMMIT();

    const int nkv = N_ / FBN;
    for (int s = 0; s < nkv; s++) {
        if (s + 1 < nkv) { load_stage(s + 1); CP_COMMIT(); CP_WAIT(1); }
        else             { CP_WAIT(0); }
        __syncthreads();

        const uint32_t kb = sb + (uint32_t)(s & 1) * FSTAGE;
        const uint32_t vb = kb + FTILE;

        float sacc[8][4];
#pragma unroll
        for (int nt = 0; nt < 8; nt++)
#pragma unroll
            for (int i = 0; i < 4; i++) sacc[nt][i] = 0.f;

#pragma unroll
        for (int j = 0; j < 6; j++) {
            uint32_t bf[8][2];
#pragma unroll
            for (int np = 0; np < 4; np++) {
                const int sel = lane >> 3;
                const uint32_t row = (uint32_t)(np * 16 + ((sel & 2) ? 8 : 0) + (lane & 7));
                const uint32_t col = (uint32_t)(j * 16 + ((sel & 1) ? 8 : 0));
                const uint32_t ad = kb + row * FSTRIDE + col * 2;
                LDMX4(bf[2*np][0], bf[2*np][1], bf[2*np+1][0], bf[2*np+1][1], ad);
            }
#pragma unroll
            for (int nt = 0; nt < 8; nt++) {
                mma_f16(sacc[nt], qa_h[j], bf[nt]);
                mma_f16(sacc[nt], qa_l[j], bf[nt]);
            }
        }

        float mx0 = -1e30f, mx1 = -1e30f;
#pragma unroll
        for (int nt = 0; nt < 8; nt++) {
            mx0 = fmaxf(mx0, fmaxf(sacc[nt][0], sacc[nt][1]));
            mx1 = fmaxf(mx1, fmaxf(sacc[nt][2], sacc[nt][3]));
        }
        mx0 = fmaxf(mx0, __shfl_xor_sync(0xffffffffu, mx0, 1));
        mx0 = fmaxf(mx0, __shfl_xor_sync(0xffffffffu, mx0, 2));
        mx1 = fmaxf(mx1, __shfl_xor_sync(0xffffffffu, mx1, 1));
        mx1 = fmaxf(mx1, __shfl_xor_sync(0xffffffffu, mx1, 2));

        const float mn0 = fmaxf(mrow0, mx0), mn1 = fmaxf(mrow1, mx1);
        const float corr0 = __expf(mrow0 - mn0), corr1 = __expf(mrow1 - mn1);
        mrow0 = mn0; mrow1 = mn1;

        float sum0 = 0.f, sum1 = 0.f;
#pragma unroll
        for (int nt = 0; nt < 8; nt++) {
            sacc[nt][0] = __expf(sacc[nt][0] - mn0);
            sacc[nt][1] = __expf(sacc[nt][1] - mn0);
            sacc[nt][2] = __expf(sacc[nt][2] - mn1);
            sacc[nt][3] = __expf(sacc[nt][3] - mn1);
            sum0 += sacc[nt][0] + sacc[nt][1];
            sum1 += sacc[nt][2] + sacc[nt][3];
        }
        lrow0 = lrow0 * corr0 + sum0;
        lrow1 = lrow1 * corr1 + sum1;
#pragma unroll
        for (int ot = 0; ot < 12; ot++) {
            oacc[ot][0] *= corr0; oacc[ot][1] *= corr0;
            oacc[ot][2] *= corr1; oacc[ot][3] *= corr1;
        }

        // ---- O += P V (P single fp16; see R10 error analysis) ----
#pragma unroll
        for (int jj = 0; jj < 4; jj++) {
            uint32_t pa[4];
            pa[0] = pk_h2(sacc[2*jj][0],   sacc[2*jj][1]);
            pa[1] = pk_h2(sacc[2*jj][2],   sacc[2*jj][3]);
            pa[2] = pk_h2(sacc[2*jj+1][0], sacc[2*jj+1][1]);
            pa[3] = pk_h2(sacc[2*jj+1][2], sacc[2*jj+1][3]);
#pragma unroll
            for (int np = 0; np < 6; np++) {
                uint32_t vf[2][2];
                const int sel = lane >> 3;
                const uint32_t row = (uint32_t)(jj * 16 + ((sel & 1) ? 8 : 0) + (lane & 7));
                const uint32_t col = (uint32_t)(np * 16 + ((sel & 2) ? 8 : 0));
                const uint32_t ad = vb + row * FSTRIDE + col * 2;
                LDMX4T(vf[0][0], vf[0][1], vf[1][0], vf[1][1], ad);
                mma_f16(oacc[2*np],   pa, vf[0]);
                mma_f16(oacc[2*np+1], pa, vf[1]);
            }
        }
        __syncthreads();
    }

    lrow0 += __shfl_xor_sync(0xffffffffu, lrow0, 1);
    lrow0 += __shfl_xor_sync(0xffffffffu, lrow0, 2);
    lrow1 += __shfl_xor_sync(0xffffffffu, lrow1, 1);
    lrow1 += __shfl_xor_sync(0xffffffffu, lrow1, 2);
    const float inv0 = 1.f / lrow0, inv1 = 1.f / lrow1;

    const int nrow = m0 + wid * 16 + g;
    const size_t ob0 = (size_t)(b * N_ + nrow) * HDH + h * DH_;
    const size_t ob1 = (size_t)(b * N_ + nrow + 8) * HDH + h * DH_;
#pragma unroll
    for (int ot = 0; ot < 12; ot++) {
        const int d0 = ot * 8 + tg * 2;
        const float f00 = oacc[ot][0] * inv0, f01 = oacc[ot][1] * inv0;
        const float f10 = oacc[ot][2] * inv1, f11 = oacc[ot][3] * inv1;
        const __half h00 = __float2half(f00), h01 = __float2half(f01);
        const __half h10 = __float2half(f10), h11 = __float2half(f11);
        *(__half2*)(g_chi + ob0 + d0) = __halves2half2(h00, h01);
        *(__half2*)(g_clo + ob0 + d0) =
            __floats2half2_rn(f00 - __half2float(h00), f01 - __half2float(h01));
        *(__half2*)(g_chi + ob1 + d0) = __halves2half2(h10, h11);
        *(__half2*)(g_clo + ob1 + d0) =
            __floats2half2_rn(f10 - __half2float(h10), f11 - __half2float(h11));
    }
}

// ------------------------------------------------------------------
extern "C" void kernel_launch(void* const* d_in, const int* in_sizes, int n_in,
                              void* d_out, int out_size) {
    const float* x    = (const float*)d_in[0];
    const float* f1   = (const float*)d_in[1];
    const float* f2   = (const float*)d_in[2];
    const float* f3   = (const float*)d_in[3];
    const float* Wqkv = (const float*)d_in[4];
    const float* Wout = (const float*)d_in[5];
    const float* bout = (const float*)d_in[6];
    float* out = (float*)d_out;

    __half *xhi, *xlo, *chi, *clo, *wqt, *wot;
    cudaGetSymbolAddress((void**)&xhi, g_xhi);
    cudaGetSymbolAddress((void**)&xlo, g_xlo);
    cudaGetSymbolAddress((void**)&chi, g_chi);
    cudaGetSymbolAddress((void**)&clo, g_clo);
    cudaGetSymbolAddress((void**)&wqt, g_wqt);
    cudaGetSymbolAddress((void**)&wot, g_wot);

    cudaFuncSetAttribute(gemm_mma<0>, cudaFuncAttributeMaxDynamicSharedMemorySize, GEMM_SMEM);
    cudaFuncSetAttribute(gemm_mma<1>, cudaFuncAttributeMaxDynamicSharedMemorySize, GEMM_SMEM);
    cudaFuncSetAttribute(flash_mma, cudaFuncAttributeMaxDynamicSharedMemorySize, FLASH_SMEM);

    // 0) cos/sin table
    cs_init<<<(3 * N_ * 32 + 255) / 256, 256>>>(f1, f2, f3);

    // 1) x -> fp16 hi/lo; weights -> transposed fp16
    cvt_hilo<<<(M_ * DIM_ / 4 + 255) / 256, 256>>>(x, xhi, xlo, M_ * DIM_ / 4);
    transpose_f16<<<dim3(QKV3 / 32, DIM_ / 32), dim3(32, 8)>>>(Wqkv, wqt, DIM_, QKV3);
    transpose_f16<<<dim3(HDH / 32, HDH / 32), dim3(32, 8)>>>(Wout, wot, HDH, HDH);

    // 2) QKV GEMM with fused RoPE + head-transpose epilogue
    gemm_mma<1><<<dim3(QKV3 / 128, M_ / 128), 256, GEMM_SMEM>>>(
        xhi, xlo, wqt, nullptr, nullptr, QKV3, DIM_);

    // 3) Flash attention (writes ctx hi/lo fp16 directly)
    flash_mma<<<dim3(N_ / FBM, B_ * H_), 256, FLASH_SMEM>>>();

    // 4) Output GEMM + bias
    gemm_mma<0><<<dim3(HDH / 128, M_ / 128), 256, GEMM_SMEM>>>(
        chi, clo, wot, bout, out, HDH, HDH);
}

// round 11
// speedup vs baseline: 1.1935x; 1.0968x over previous
#include <cuda_runtime.h>
#include <cuda_fp16.h>
#include <cstdint>

#define B_    4
#define N_    2048
#define DIM_  1536
#define H_    16
#define DH_   96
#define QKV3  4608      // 3*H*DH
#define HDH   1536      // H*DH
#define M_    (B_*N_)   // 8192
#define SCALE_ 0.10206207261596575f  // 96^-0.5

// ---------------- scratch (no allocations allowed) ----------------
__device__ __half g_xhi[(size_t)M_ * DIM_];
__device__ __half g_xlo[(size_t)M_ * DIM_];
__device__ __half g_chi[(size_t)M_ * HDH];
__device__ __half g_wqt[(size_t)QKV3 * DIM_];        // W^T [N,K] single fp16
__device__ __half g_wot[(size_t)HDH * HDH];

// q hi/lo; k, v single fp16. layout [b*H + h][n][d]; q pre-scaled
#define PER_T ((size_t)B_ * H_ * N_ * DH_)
__device__ __half g_qh[PER_T];
__device__ __half g_ql[PER_T];
__device__ __half g_kk[PER_T];
__device__ __half g_vv[PER_T];

// cos/sin table: [chunk(3)][n(2048)][j(32)] -> (cos f, sin f)
__device__ float2 g_cs[3 * N_ * 32];

// ================= helpers (sm_80+ only) ==========================
__device__ __forceinline__ uint32_t smem_u32(const void* p) {
    uint32_t a;
    asm("{ .reg .u64 t; cvta.to.shared.u64 t, %1; cvt.u32.u64 %0, t; }"
        : "=r"(a) : "l"(p));
    return a;
}
#define CP_ASYNC16(saddr, gptr) \
    asm volatile("cp.async.cg.shared.global [%0], [%1], 16;" :: "r"(saddr), "l"(gptr))
#define CP_COMMIT() asm volatile("cp.async.commit_group;" ::: "memory")
#define CP_WAIT(n)  asm volatile("cp.async.wait_group %0;" :: "n"(n) : "memory")

#define LDMX4(r0,r1,r2,r3,addr) \
    asm volatile("ldmatrix.sync.aligned.m8n8.x4.shared.b16 {%0,%1,%2,%3}, [%4];" \
        : "=r"(r0),"=r"(r1),"=r"(r2),"=r"(r3) : "r"(addr))
#define LDMX4T(r0,r1,r2,r3,addr) \
    asm volatile("ldmatrix.sync.aligned.m8n8.x4.trans.shared.b16 {%0,%1,%2,%3}, [%4];" \
        : "=r"(r0),"=r"(r1),"=r"(r2),"=r"(r3) : "r"(addr))

__device__ __forceinline__ void mma_f16(float* c, const uint32_t* a, const uint32_t* b) {
    asm volatile(
        "mma.sync.aligned.m16n8k16.row.col.f32.f16.f16.f32 "
        "{%0,%1,%2,%3}, {%4,%5,%6,%7}, {%8,%9}, {%0,%1,%2,%3};"
        : "+f"(c[0]), "+f"(c[1]), "+f"(c[2]), "+f"(c[3])
        : "r"(a[0]), "r"(a[1]), "r"(a[2]), "r"(a[3]), "r"(b[0]), "r"(b[1]));
}
__device__ __forceinline__ uint32_t pk_h2(float a, float b) {
    __half2 t = __floats2half2_rn(a, b);
    return *(uint32_t*)&t;
}

// ---- cos/sin table init --------------------------------------------
__global__ void cs_init(const float* __restrict__ f1, const float* __restrict__ f2,
                        const float* __restrict__ f3) {
    const int i = blockIdx.x * 256 + threadIdx.x;
    if (i >= 3 * N_ * 32) return;
    const int chunk = i / (N_ * 32);
    const int rem = i - chunk * (N_ * 32);
    const float* f = (chunk == 0) ? f1 : ((chunk == 1) ? f2 : f3);
    const float fr = f[rem];
    g_cs[i] = make_float2(cosf(fr), sinf(fr));
}

// ====== fp16 mma.sync GEMM (TERMS=1 or 2 activation terms) ========
// ROPE=0: C = A@Wt^T + bias (fp32 out).
// ROPE=1: QKV gemm; epilogue applies RoPE + head transpose, writes
//         g_qh/g_ql (scaled), g_kk, g_vv fp16 directly.
#define GS_STRIDE 80
#define GS_TILE   10240

template <int ROPE, int TERMS>
__global__ void __launch_bounds__(256, 2)
gemm_mma(const __half* __restrict__ Ahi, const __half* __restrict__ Alo,
         const __half* __restrict__ Wt,
         const float* __restrict__ bias, float* __restrict__ C, int N, int K) {
    extern __shared__ char sm_[];
    const uint32_t sb = smem_u32(sm_);
    const int tid = threadIdx.x;
    const int wid = tid >> 5, lane = tid & 31;
    const int g = lane >> 2, tg = lane & 3;
    const int wm = wid & 3, wn = wid >> 2;
    const int brow = blockIdx.y * 128;
    const int bcol = blockIdx.x * 128;

    const uint32_t STAGE = (uint32_t)(TERMS + 1) * GS_TILE;
    const uint32_t WOFF  = (uint32_t)TERMS * GS_TILE;

    const int lane7 = lane & 7, sel = lane >> 3;
    const uint32_t a_rowadd = (uint32_t)(lane7 + ((sel & 1) ? 8 : 0));
    const uint32_t a_colb   = (uint32_t)(((sel >> 1) ? 8 : 0) * 2);
    const uint32_t b_rowadd = (uint32_t)(lane7 + ((sel & 2) ? 8 : 0));
    const uint32_t b_colb   = (uint32_t)(((sel & 1) ? 8 : 0) * 2);

    float acc[2][8][4];
#pragma unroll
    for (int mt = 0; mt < 2; mt++)
#pragma unroll
        for (int nt = 0; nt < 8; nt++)
#pragma unroll
            for (int i = 0; i < 4; i++) acc[mt][nt][i] = 0.f;

    const int nst = K / 32;

    auto load_stage = [&](int s) {
        const uint32_t base = sb + (uint32_t)(s & 1) * STAGE;
        const int k0 = s * 32;
        const int nch = (TERMS == 2) ? 6 : 4;
#pragma unroll
        for (int i = 0; i < 6; i++) {
            if (i >= nch) break;
            const int idx = tid + i * 256;
            const int tile = idx >> 9;           // 0..TERMS
            const int w = idx & 511;
            const int r = w >> 2, c = w & 3;
            const uint32_t so = base + (uint32_t)tile * GS_TILE +
                                (uint32_t)r * GS_STRIDE + (uint32_t)c * 16;
            const char* gp;
            if (tile == 0)                      gp = (const char*)Ahi + ((size_t)(brow + r) * K + k0 + c * 8) * 2;
            else if (TERMS == 2 && tile == 1)   gp = (const char*)Alo + ((size_t)(brow + r) * K + k0 + c * 8) * 2;
            else                                gp = (const char*)Wt  + ((size_t)(bcol + r) * K + k0 + c * 8) * 2;
            CP_ASYNC16(so, gp);
        }
    };

    load_stage(0); CP_COMMIT();

    for (int s = 0; s < nst; s++) {
        if (s + 1 < nst) { load_stage(s + 1); CP_COMMIT(); CP_WAIT(1); }
        else             { CP_WAIT(0); }
        __syncthreads();

        const uint32_t base = sb + (uint32_t)(s & 1) * STAGE;
#pragma unroll
        for (int kk = 0; kk < 2; kk++) {
            const uint32_t kb = (uint32_t)(kk * 16) * 2;
            uint32_t ah[2][4], al[2][4], bw[8][2];
#pragma unroll
            for (int mt = 0; mt < 2; mt++) {
                const uint32_t ar = base + (uint32_t)(wm * 32 + mt * 16 + a_rowadd) * GS_STRIDE
                                  + kb + a_colb;
                LDMX4(ah[mt][0], ah[mt][1], ah[mt][2], ah[mt][3], ar);
                if (TERMS == 2)
                    LDMX4(al[mt][0], al[mt][1], al[mt][2], al[mt][3], ar + GS_TILE);
            }
#pragma unroll
            for (int nb = 0; nb < 4; nb++) {
                const uint32_t br = base + WOFF
                                  + (uint32_t)(wn * 64 + nb * 16 + b_rowadd) * GS_STRIDE
                                  + kb + b_colb;
                LDMX4(bw[2*nb][0], bw[2*nb][1], bw[2*nb+1][0], bw[2*nb+1][1], br);
            }
#pragma unroll
            for (int mt = 0; mt < 2; mt++)
#pragma unroll
                for (int nt = 0; nt < 8; nt++) {
                    mma_f16(acc[mt][nt], ah[mt], bw[nt]);
                    if (TERMS == 2) mma_f16(acc[mt][nt], al[mt], bw[nt]);
                }
        }
        __syncthreads();
    }

    if (ROPE) {
        const int which = bcol / HDH;   // 0=q 1=k 2=v
#pragma unroll
        for (int mt = 0; mt < 2; mt++) {
#pragma unroll
            for (int hf = 0; hf < 2; hf++) {
                const int row = brow + wm * 32 + mt * 16 + g + hf * 8;
                const int bb = row >> 11, n = row & (N_ - 1);
                const int i0 = hf * 2;
#pragma unroll
                for (int pp = 0; pp < 4; pp++) {
                    const int ntA = (pp >> 1) * 4 + (pp & 1);
                    const int ntB = ntA + 2;
                    const int cA = bcol + wn * 64 + ntA * 8 + tg * 2;
                    const int cq = cA - which * HDH;
                    const int hh = cq / DH_;
                    const int dA = cq - hh * DH_;
                    const int jA = dA & 31;
                    const int chunk = dA >> 5;
                    const float a0 = acc[mt][ntA][i0], a1 = acc[mt][ntA][i0 + 1];
                    const float b0 = acc[mt][ntB][i0], b1 = acc[mt][ntB][i0 + 1];
                    float oA0, oA1, oB0, oB1;
                    if (which == 2) {
                        oA0 = a0; oA1 = a1; oB0 = b0; oB1 = b1;
                    } else {
                        const float2* csp = g_cs + (size_t)(chunk * N_ + n) * 32;
                        const float2 cA0 = csp[jA],      cA1 = csp[jA + 1];
                        const float2 cB0 = csp[jA + 16], cB1 = csp[jA + 17];
                        oA0 = a0 * cA0.x - b0 * cA0.y;
                        oA1 = a1 * cA1.x - b1 * cA1.y;
                        oB0 = b0 * cB0.x + a0 * cB0.y;
                        oB1 = b1 * cB1.x + a1 * cB1.y;
                        if (which == 0) {
                            oA0 *= SCALE_; oA1 *= SCALE_; oB0 *= SCALE_; oB1 *= SCALE_;
                        }
                    }
                    const size_t oA = ((size_t)((bb * H_ + hh) * N_ + n)) * DH_ + dA;
                    const size_t oB = oA + 16;
                    if (which == 0) {
                        const __half hA0 = __float2half(oA0), hA1 = __float2half(oA1);
                        const __half hB0 = __float2half(oB0), hB1 = __float2half(oB1);
                        *(__half2*)(g_qh + oA) = __halves2half2(hA0, hA1);
                        *(__half2*)(g_ql + oA) =
                            __floats2half2_rn(oA0 - __half2float(hA0), oA1 - __half2float(hA1));
                        *(__half2*)(g_qh + oB) = __halves2half2(hB0, hB1);
                        *(__half2*)(g_ql + oB) =
                            __floats2half2_rn(oB0 - __half2float(hB0), oB1 - __half2float(hB1));
                    } else if (which == 1) {
                        *(__half2*)(g_kk + oA) = __floats2half2_rn(oA0, oA1);
                        *(__half2*)(g_kk + oB) = __floats2half2_rn(oB0, oB1);
                    } else {
                        *(__half2*)(g_vv + oA) = __floats2half2_rn(oA0, oA1);
                        *(__half2*)(g_vv + oB) = __floats2half2_rn(oB0, oB1);
                    }
                }
            }
        }
    } else {
#pragma unroll
        for (int mt = 0; mt < 2; mt++) {
            const int r0 = brow + wm * 32 + mt * 16 + g;
#pragma unroll
            for (int nt = 0; nt < 8; nt++) {
                const int c = bcol + wn * 64 + nt * 8 + tg * 2;
                float2 v0 = make_float2(acc[mt][nt][0], acc[mt][nt][1]);
                float2 v1 = make_float2(acc[mt][nt][2], acc[mt][nt][3]);
                const float b0 = bias[c], b1 = bias[c + 1];
                v0.x += b0; v0.y += b1; v1.x += b0; v1.y += b1;
                *(float2*)(C + (size_t)r0 * N + c)       = v0;
                *(float2*)(C + (size_t)(r0 + 8) * N + c) = v1;
            }
        }
    }
}

#define GEMM_SMEM_2T (2 * 3 * GS_TILE)   // 61440
#define GEMM_SMEM_1T (2 * 2 * GS_TILE)   // 40960

// ---------------- fp32 -> fp16 hi/lo ------------------------------
__global__ void cvt_hilo(const float* __restrict__ src,
                         __half* __restrict__ hi, __half* __restrict__ lo, int n4) {
    const int i = blockIdx.x * blockDim.x + threadIdx.x;
    if (i >= n4) return;
    const float4 v = ((const float4*)src)[i];
    const __half h0 = __float2half(v.x), h1 = __float2half(v.y);
    const __half h2 = __float2half(v.z), h3 = __float2half(v.w);
    ((__half2*)hi)[i * 2]     = __halves2half2(h0, h1);
    ((__half2*)hi)[i * 2 + 1] = __halves2half2(h2, h3);
    ((__half2*)lo)[i * 2]     = __floats2half2_rn(v.x - __half2float(h0), v.y - __half2float(h1));
    ((__half2*)lo)[i * 2 + 1] = __floats2half2_rn(v.z - __half2float(h2), v.w - __half2float(h3));
}

// W [K,N] -> W^T [N,K] single fp16
__global__ void transpose_f16(const float* __restrict__ W,
                              __half* __restrict__ Wt, int K, int N) {
    __shared__ float t[32][33];
    const int n0 = blockIdx.x * 32, k0 = blockIdx.y * 32;
    const int tx = threadIdx.x;
    for (int y = threadIdx.y; y < 32; y += 8)
        t[y][tx] = W[(size_t)(k0 + y) * N + n0 + tx];
    __syncthreads();
    for (int y = threadIdx.y; y < 32; y += 8)
        Wt[(size_t)(n0 + y) * K + k0 + tx] = __float2half(t[tx][y]);
}

// ---------------- Flash attention (fp16 mma.sync) -----------------
// Q 2-term (hi/lo); K, V, P single fp16. Writes ctx single fp16.
#define FBM    128
#define FBN    64
#define FSTRIDE 208
#define FTILE  (64 * FSTRIDE)
#define FSTAGE (2 * FTILE)
#define FLASH_SMEM (2 * FSTAGE)

__global__ void __launch_bounds__(256, 1) flash_mma() {
    extern __shared__ char sm_[];
    const uint32_t sb = smem_u32(sm_);
    const int tid = threadIdx.x;
    const int wid = tid >> 5, lane = tid & 31;
    const int g = lane >> 2, tg = lane & 3;
    const int bh = blockIdx.y;
    const int b  = bh >> 4, h = bh & 15;
    const int m0 = blockIdx.x * FBM;

    const size_t tbase = (size_t)bh * N_ * DH_;

    const int qrow = m0 + wid * 16 + g;
    const char* qh = (const char*)(g_qh + tbase + (size_t)qrow * DH_);
    const char* ql = (const char*)(g_ql + tbase + (size_t)qrow * DH_);
    uint32_t qa_h[6][4], qa_l[6][4];
#pragma unroll
    for (int j = 0; j < 6; j++) {
        const int c0 = (j * 16 + tg * 2) * 2;
        qa_h[j][0] = *(const uint32_t*)(qh + c0);
        qa_h[j][1] = *(const uint32_t*)(qh + 8 * DH_ * 2 + c0);
        qa_h[j][2] = *(const uint32_t*)(qh + c0 + 16);
        qa_h[j][3] = *(const uint32_t*)(qh + 8 * DH_ * 2 + c0 + 16);
        qa_l[j][0] = *(const uint32_t*)(ql + c0);
        qa_l[j][1] = *(const uint32_t*)(ql + 8 * DH_ * 2 + c0);
        qa_l[j][2] = *(const uint32_t*)(ql + c0 + 16);
        qa_l[j][3] = *(const uint32_t*)(ql + 8 * DH_ * 2 + c0 + 16);
    }

    float oacc[12][4];
#pragma unroll
    for (int ot = 0; ot < 12; ot++)
#pragma unroll
        for (int i = 0; i < 4; i++) oacc[ot][i] = 0.f;
    float mrow0 = -1e30f, mrow1 = -1e30f, lrow0 = 0.f, lrow1 = 0.f;

    const char* srcK = (const char*)(g_kk + tbase);
    const char* srcV = (const char*)(g_vv + tbase);

    auto load_stage = [&](int s) {
        const uint32_t base = sb + (uint32_t)(s & 1) * FSTAGE;
        const int n0 = s * FBN;
#pragma unroll
        for (int i = 0; i < 6; i++) {
            const int idx = tid + i * 256;
            const int tile = idx / 768;
            const int w = idx % 768;
            const int r = w / 12, c = w % 12;
            const uint32_t so = base + (uint32_t)tile * FTILE +
                                (uint32_t)r * FSTRIDE + (uint32_t)c * 16;
            const size_t go = ((size_t)(n0 + r) * DH_ + c * 8) * 2;
            CP_ASYNC16(so, (tile == 0 ? srcK : srcV) + go);
        }
    };

    load_stage(0); CP_COMMIT();

    const int nkv = N_ / FBN;
    for (int s = 0; s < nkv; s++) {
        if (s + 1 < nkv) { load_stage(s + 1); CP_COMMIT(); CP_WAIT(1); }
        else             { CP_WAIT(0); }
        __syncthreads();

        const uint32_t kb = sb + (uint32_t)(s & 1) * FSTAGE;
        const uint32_t vb = kb + FTILE;

        float sacc[8][4];
#pragma unroll
        for (int nt = 0; nt < 8; nt++)
#pragma unroll
            for (int i = 0; i < 4; i++) sacc[nt][i] = 0.f;

#pragma unroll
        for (int j = 0; j < 6; j++) {
            uint32_t bf[8][2];
#pragma unroll
            for (int np = 0; np < 4; np++) {
                const int sel = lane >> 3;
                const uint32_t row = (uint32_t)(np * 16 + ((sel & 2) ? 8 : 0) + (lane & 7));
                const uint32_t col = (uint32_t)(j * 16 + ((sel & 1) ? 8 : 0));
                const uint32_t ad = kb + row * FSTRIDE + col * 2;
                LDMX4(bf[2*np][0], bf[2*np][1], bf[2*np+1][0], bf[2*np+1][1], ad);
            }
#pragma unroll
            for (int nt = 0; nt < 8; nt++) {
                mma_f16(sacc[nt], qa_h[j], bf[nt]);
                mma_f16(sacc[nt], qa_l[j], bf[nt]);
            }
        }

        float mx0 = -1e30f, mx1 = -1e30f;
#pragma unroll
        for (int nt = 0; nt < 8; nt++) {
            mx0 = fmaxf(mx0, fmaxf(sacc[nt][0], sacc[nt][1]));
            mx1 = fmaxf(mx1, fmaxf(sacc[nt][2], sacc[nt][3]));
        }
        mx0 = fmaxf(mx0, __shfl_xor_sync(0xffffffffu, mx0, 1));
        mx0 = fmaxf(mx0, __shfl_xor_sync(0xffffffffu, mx0, 2));
        mx1 = fmaxf(mx1, __shfl_xor_sync(0xffffffffu, mx1, 1));
        mx1 = fmaxf(mx1, __shfl_xor_sync(0xffffffffu, mx1, 2));

        const float mn0 = fmaxf(mrow0, mx0), mn1 = fmaxf(mrow1, mx1);
        const float corr0 = __expf(mrow0 - mn0), corr1 = __expf(mrow1 - mn1);
        mrow0 = mn0; mrow1 = mn1;

        float sum0 = 0.f, sum1 = 0.f;
#pragma unroll
        for (int nt = 0; nt < 8; nt++) {
            sacc[nt][0] = __expf(sacc[nt][0] - mn0);
            sacc[nt][1] = __expf(sacc[nt][1] - mn0);
            sacc[nt][2] = __expf(sacc[nt][2] - mn1);
            sacc[nt][3] = __expf(sacc[nt][3] - mn1);
            sum0 += sacc[nt][0] + sacc[nt][1];
            sum1 += sacc[nt][2] + sacc[nt][3];
        }
        lrow0 = lrow0 * corr0 + sum0;
        lrow1 = lrow1 * corr1 + sum1;
#pragma unroll
        for (int ot = 0; ot < 12; ot++) {
            oacc[ot][0] *= corr0; oacc[ot][1] *= corr0;
            oacc[ot][2] *= corr1; oacc[ot][3] *= corr1;
        }

        // ---- O += P V (P single fp16) ----
#pragma unroll
        for (int jj = 0; jj < 4; jj++) {
            uint32_t pa[4];
            pa[0] = pk_h2(sacc[2*jj][0],   sacc[2*jj][1]);
            pa[1] = pk_h2(sacc[2*jj][2],   sacc[2*jj][3]);
            pa[2] = pk_h2(sacc[2*jj+1][0], sacc[2*jj+1][1]);
            pa[3] = pk_h2(sacc[2*jj+1][2], sacc[2*jj+1][3]);
#pragma unroll
            for (int np = 0; np < 6; np++) {
                uint32_t vf[2][2];
                const int sel = lane >> 3;
                const uint32_t row = (uint32_t)(jj * 16 + ((sel & 1) ? 8 : 0) + (lane & 7));
                const uint32_t col = (uint32_t)(np * 16 + ((sel & 2) ? 8 : 0));
                const uint32_t ad = vb + row * FSTRIDE + col * 2;
                LDMX4T(vf[0][0], vf[0][1], vf[1][0], vf[1][1], ad);
                mma_f16(oacc[2*np],   pa, vf[0]);
                mma_f16(oacc[2*np+1], pa, vf[1]);
            }
        }
        __syncthreads();
    }

    lrow0 += __shfl_xor_sync(0xffffffffu, lrow0, 1);
    lrow0 += __shfl_xor_sync(0xffffffffu, lrow0, 2);
    lrow1 += __shfl_xor_sync(0xffffffffu, lrow1, 1);
    lrow1 += __shfl_xor_sync(0xffffffffu, lrow1, 2);
    const float inv0 = 1.f / lrow0, inv1 = 1.f / lrow1;

    const int nrow = m0 + wid * 16 + g;
    const size_t ob0 = (size_t)(b * N_ + nrow) * HDH + h * DH_;
    const size_t ob1 = (size_t)(b * N_ + nrow + 8) * HDH + h * DH_;
#pragma unroll
    for (int ot = 0; ot < 12; ot++) {
        const int d0 = ot * 8 + tg * 2;
        *(__half2*)(g_chi + ob0 + d0) =
            __floats2half2_rn(oacc[ot][0] * inv0, oacc[ot][1] * inv0);
        *(__half2*)(g_chi + ob1 + d0) =
            __floats2half2_rn(oacc[ot][2] * inv1, oacc[ot][3] * inv1);
    }
}

// ------------------------------------------------------------------
extern "C" void kernel_launch(void* const* d_in, const int* in_sizes, int n_in,
                              void* d_out, int out_size) {
    const float* x    = (const float*)d_in[0];
    const float* f1   = (const float*)d_in[1];
    const float* f2   = (const float*)d_in[2];
    const float* f3   = (const float*)d_in[3];
    const float* Wqkv = (const float*)d_in[4];
    const float* Wout = (const float*)d_in[5];
    const float* bout = (const float*)d_in[6];
    float* out = (float*)d_out;

    __half *xhi, *xlo, *chi, *wqt, *wot;
    cudaGetSymbolAddress((void**)&xhi, g_xhi);
    cudaGetSymbolAddress((void**)&xlo, g_xlo);
    cudaGetSymbolAddress((void**)&chi, g_chi);
    cudaGetSymbolAddress((void**)&wqt, g_wqt);
    cudaGetSymbolAddress((void**)&wot, g_wot);

    cudaFuncSetAttribute((const void*)gemm_mma<1, 2>,
                         cudaFuncAttributeMaxDynamicSharedMemorySize, GEMM_SMEM_2T);
    cudaFuncSetAttribute((const void*)gemm_mma<0, 1>,
                         cudaFuncAttributeMaxDynamicSharedMemorySize, GEMM_SMEM_1T);
    cudaFuncSetAttribute((const void*)flash_mma,
                         cudaFuncAttributeMaxDynamicSharedMemorySize, FLASH_SMEM);

    // 0) cos/sin table
    cs_init<<<(3 * N_ * 32 + 255) / 256, 256>>>(f1, f2, f3);

    // 1) x -> fp16 hi/lo; weights -> transposed fp16
    cvt_hilo<<<(M_ * DIM_ / 4 + 255) / 256, 256>>>(x, xhi, xlo, M_ * DIM_ / 4);
    transpose_f16<<<dim3(QKV3 / 32, DIM_ / 32), dim3(32, 8)>>>(Wqkv, wqt, DIM_, QKV3);
    transpose_f16<<<dim3(HDH / 32, HDH / 32), dim3(32, 8)>>>(Wout, wot, HDH, HDH);

    // 2) QKV GEMM (2-term) with fused RoPE + head-transpose epilogue
    gemm_mma<1, 2><<<dim3(QKV3 / 128, M_ / 128), 256, GEMM_SMEM_2T>>>(
        xhi, xlo, wqt, nullptr, nullptr, QKV3, DIM_);

    // 3) Flash attention (writes ctx single fp16)
    flash_mma<<<dim3(N_ / FBM, B_ * H_), 256, FLASH_SMEM>>>();

    // 4) Output GEMM (1-term) + bias
    gemm_mma<0, 1><<<dim3(HDH / 128, M_ / 128), 256, GEMM_SMEM_1T>>>(
        chi, nullptr, wot, bout, out, HDH, HDH);
}

// round 12
// speedup vs baseline: 1.4970x; 1.2544x over previous
#include <cuda_runtime.h>
#include <cuda_fp16.h>
#include <cstdint>

#define B_    4
#define N_    2048
#define DIM_  1536
#define H_    16
#define DH_   96
#define QKV3  4608      // 3*H*DH
#define HDH   1536      // H*DH
#define M_    (B_*N_)   // 8192
#define SCALE_ 0.10206207261596575f  // 96^-0.5

// ---------------- scratch (no allocations allowed) ----------------
__device__ __half g_xh [(size_t)M_ * DIM_];
__device__ __half g_chi[(size_t)M_ * HDH];
__device__ __half g_wqt[(size_t)QKV3 * DIM_];        // W^T [N,K] single fp16
__device__ __half g_wot[(size_t)HDH * HDH];

// q hi/lo; k, v single fp16. layout [b*H + h][n][d]; q pre-scaled
#define PER_T ((size_t)B_ * H_ * N_ * DH_)
__device__ __half g_qh[PER_T];
__device__ __half g_ql[PER_T];
__device__ __half g_kk[PER_T];
__device__ __half g_vv[PER_T];

// cos/sin table: [chunk(3)][n(2048)][j(32)] -> (cos f, sin f)
__device__ float2 g_cs[3 * N_ * 32];

// ================= helpers (sm_80+ only) ==========================
__device__ __forceinline__ uint32_t smem_u32(const void* p) {
    uint32_t a;
    asm("{ .reg .u64 t; cvta.to.shared.u64 t, %1; cvt.u32.u64 %0, t; }"
        : "=r"(a) : "l"(p));
    return a;
}
#define CP_ASYNC16(saddr, gptr) \
    asm volatile("cp.async.cg.shared.global [%0], [%1], 16;" :: "r"(saddr), "l"(gptr))
#define CP_COMMIT() asm volatile("cp.async.commit_group;" ::: "memory")
#define CP_WAIT(n)  asm volatile("cp.async.wait_group %0;" :: "n"(n) : "memory")

#define LDMX4(r0,r1,r2,r3,addr) \
    asm volatile("ldmatrix.sync.aligned.m8n8.x4.shared.b16 {%0,%1,%2,%3}, [%4];" \
        : "=r"(r0),"=r"(r1),"=r"(r2),"=r"(r3) : "r"(addr))
#define LDMX4T(r0,r1,r2,r3,addr) \
    asm volatile("ldmatrix.sync.aligned.m8n8.x4.trans.shared.b16 {%0,%1,%2,%3}, [%4];" \
        : "=r"(r0),"=r"(r1),"=r"(r2),"=r"(r3) : "r"(addr))

__device__ __forceinline__ void mma_f16(float* c, const uint32_t* a, const uint32_t* b) {
    asm volatile(
        "mma.sync.aligned.m16n8k16.row.col.f32.f16.f16.f32 "
        "{%0,%1,%2,%3}, {%4,%5,%6,%7}, {%8,%9}, {%0,%1,%2,%3};"
        : "+f"(c[0]), "+f"(c[1]), "+f"(c[2]), "+f"(c[3])
        : "r"(a[0]), "r"(a[1]), "r"(a[2]), "r"(a[3]), "r"(b[0]), "r"(b[1]));
}
__device__ __forceinline__ uint32_t pk_h2(float a, float b) {
    __half2 t = __floats2half2_rn(a, b);
    return *(uint32_t*)&t;
}

// ---- cos/sin table init --------------------------------------------
__global__ void cs_init(const float* __restrict__ f1, const float* __restrict__ f2,
                        const float* __restrict__ f3) {
    const int i = blockIdx.x * 256 + threadIdx.x;
    if (i >= 3 * N_ * 32) return;
    const int chunk = i / (N_ * 32);
    const int rem = i - chunk * (N_ * 32);
    const float* f = (chunk == 0) ? f1 : ((chunk == 1) ? f2 : f3);
    const float fr = f[rem];
    g_cs[i] = make_float2(cosf(fr), sinf(fr));
}

// ====== fp16 mma.sync GEMM (TERMS=1 or 2 activation terms) ========
// ROPE=0: C = A@Wt^T + bias (fp32 out).
// ROPE=1: QKV gemm; epilogue applies RoPE + head transpose, writes
//         g_qh/g_ql (scaled), g_kk, g_vv fp16 directly.
#define GS_STRIDE 80
#define GS_TILE   10240

template <int ROPE, int TERMS>
__global__ void __launch_bounds__(256, 2)
gemm_mma(const __half* __restrict__ Ahi, const __half* __restrict__ Alo,
         const __half* __restrict__ Wt,
         const float* __restrict__ bias, float* __restrict__ C, int N, int K) {
    extern __shared__ char sm_[];
    const uint32_t sb = smem_u32(sm_);
    const int tid = threadIdx.x;
    const int wid = tid >> 5, lane = tid & 31;
    const int g = lane >> 2, tg = lane & 3;
    const int wm = wid & 3, wn = wid >> 2;
    const int brow = blockIdx.y * 128;
    const int bcol = blockIdx.x * 128;

    const uint32_t STAGE = (uint32_t)(TERMS + 1) * GS_TILE;
    const uint32_t WOFF  = (uint32_t)TERMS * GS_TILE;

    const int lane7 = lane & 7, sel = lane >> 3;
    const uint32_t a_rowadd = (uint32_t)(lane7 + ((sel & 1) ? 8 : 0));
    const uint32_t a_colb   = (uint32_t)(((sel >> 1) ? 8 : 0) * 2);
    const uint32_t b_rowadd = (uint32_t)(lane7 + ((sel & 2) ? 8 : 0));
    const uint32_t b_colb   = (uint32_t)(((sel & 1) ? 8 : 0) * 2);

    float acc[2][8][4];
#pragma unroll
    for (int mt = 0; mt < 2; mt++)
#pragma unroll
        for (int nt = 0; nt < 8; nt++)
#pragma unroll
            for (int i = 0; i < 4; i++) acc[mt][nt][i] = 0.f;

    const int nst = K / 32;

    auto load_stage = [&](int s) {
        const uint32_t base = sb + (uint32_t)(s & 1) * STAGE;
        const int k0 = s * 32;
        const int nch = (TERMS == 2) ? 6 : 4;
#pragma unroll
        for (int i = 0; i < 6; i++) {
            if (i >= nch) break;
            const int idx = tid + i * 256;
            const int tile = idx >> 9;           // 0..TERMS
            const int w = idx & 511;
            const int r = w >> 2, c = w & 3;
            const uint32_t so = base + (uint32_t)tile * GS_TILE +
                                (uint32_t)r * GS_STRIDE + (uint32_t)c * 16;
            const char* gp;
            if (tile == 0)                      gp = (const char*)Ahi + ((size_t)(brow + r) * K + k0 + c * 8) * 2;
            else if (TERMS == 2 && tile == 1)   gp = (const char*)Alo + ((size_t)(brow + r) * K + k0 + c * 8) * 2;
            else                                gp = (const char*)Wt  + ((size_t)(bcol + r) * K + k0 + c * 8) * 2;
            CP_ASYNC16(so, gp);
        }
    };

    load_stage(0); CP_COMMIT();

    for (int s = 0; s < nst; s++) {
        if (s + 1 < nst) { load_stage(s + 1); CP_COMMIT(); CP_WAIT(1); }
        else             { CP_WAIT(0); }
        __syncthreads();

        const uint32_t base = sb + (uint32_t)(s & 1) * STAGE;
#pragma unroll
        for (int kk = 0; kk < 2; kk++) {
            const uint32_t kb = (uint32_t)(kk * 16) * 2;
            uint32_t ah[2][4], al[2][4], bw[8][2];
#pragma unroll
            for (int mt = 0; mt < 2; mt++) {
                const uint32_t ar = base + (uint32_t)(wm * 32 + mt * 16 + a_rowadd) * GS_STRIDE
                                  + kb + a_colb;
                LDMX4(ah[mt][0], ah[mt][1], ah[mt][2], ah[mt][3], ar);
                if (TERMS == 2)
                    LDMX4(al[mt][0], al[mt][1], al[mt][2], al[mt][3], ar + GS_TILE);
            }
#pragma unroll
            for (int nb = 0; nb < 4; nb++) {
                const uint32_t br = base + WOFF
                                  + (uint32_t)(wn * 64 + nb * 16 + b_rowadd) * GS_STRIDE
                                  + kb + b_colb;
                LDMX4(bw[2*nb][0], bw[2*nb][1], bw[2*nb+1][0], bw[2*nb+1][1], br);
            }
#pragma unroll
            for (int mt = 0; mt < 2; mt++)
#pragma unroll
                for (int nt = 0; nt < 8; nt++) {
                    mma_f16(acc[mt][nt], ah[mt], bw[nt]);
                    if (TERMS == 2) mma_f16(acc[mt][nt], al[mt], bw[nt]);
                }
        }
        __syncthreads();
    }

    if (ROPE) {
        const int which = bcol / HDH;   // 0=q 1=k 2=v
#pragma unroll
        for (int mt = 0; mt < 2; mt++) {
#pragma unroll
            for (int hf = 0; hf < 2; hf++) {
                const int row = brow + wm * 32 + mt * 16 + g + hf * 8;
                const int bb = row >> 11, n = row & (N_ - 1);
                const int i0 = hf * 2;
#pragma unroll
                for (int pp = 0; pp < 4; pp++) {
                    const int ntA = (pp >> 1) * 4 + (pp & 1);
                    const int ntB = ntA + 2;
                    const int cA = bcol + wn * 64 + ntA * 8 + tg * 2;
                    const int cq = cA - which * HDH;
                    const int hh = cq / DH_;
                    const int dA = cq - hh * DH_;
                    const int jA = dA & 31;
                    const int chunk = dA >> 5;
                    const float a0 = acc[mt][ntA][i0], a1 = acc[mt][ntA][i0 + 1];
                    const float b0 = acc[mt][ntB][i0], b1 = acc[mt][ntB][i0 + 1];
                    float oA0, oA1, oB0, oB1;
                    if (which == 2) {
                        oA0 = a0; oA1 = a1; oB0 = b0; oB1 = b1;
                    } else {
                        const float2* csp = g_cs + (size_t)(chunk * N_ + n) * 32;
                        const float2 cA0 = csp[jA],      cA1 = csp[jA + 1];
                        const float2 cB0 = csp[jA + 16], cB1 = csp[jA + 17];
                        oA0 = a0 * cA0.x - b0 * cA0.y;
                        oA1 = a1 * cA1.x - b1 * cA1.y;
                        oB0 = b0 * cB0.x + a0 * cB0.y;
                        oB1 = b1 * cB1.x + a1 * cB1.y;
                        if (which == 0) {
                            oA0 *= SCALE_; oA1 *= SCALE_; oB0 *= SCALE_; oB1 *= SCALE_;
                        }
                    }
                    const size_t oA = ((size_t)((bb * H_ + hh) * N_ + n)) * DH_ + dA;
                    const size_t oB = oA + 16;
                    if (which == 0) {
                        const __half hA0 = __float2half(oA0), hA1 = __float2half(oA1);
                        const __half hB0 = __float2half(oB0), hB1 = __float2half(oB1);
                        *(__half2*)(g_qh + oA) = __halves2half2(hA0, hA1);
                        *(__half2*)(g_ql + oA) =
                            __floats2half2_rn(oA0 - __half2float(hA0), oA1 - __half2float(hA1));
                        *(__half2*)(g_qh + oB) = __halves2half2(hB0, hB1);
                        *(__half2*)(g_ql + oB) =
                            __floats2half2_rn(oB0 - __half2float(hB0), oB1 - __half2float(hB1));
                    } else if (which == 1) {
                        *(__half2*)(g_kk + oA) = __floats2half2_rn(oA0, oA1);
                        *(__half2*)(g_kk + oB) = __floats2half2_rn(oB0, oB1);
                    } else {
                        *(__half2*)(g_vv + oA) = __floats2half2_rn(oA0, oA1);
                        *(__half2*)(g_vv + oB) = __floats2half2_rn(oB0, oB1);
                    }
                }
            }
        }
    } else {
#pragma unroll
        for (int mt = 0; mt < 2; mt++) {
            const int r0 = brow + wm * 32 + mt * 16 + g;
#pragma unroll
            for (int nt = 0; nt < 8; nt++) {
                const int c = bcol + wn * 64 + nt * 8 + tg * 2;
                float2 v0 = make_float2(acc[mt][nt][0], acc[mt][nt][1]);
                float2 v1 = make_float2(acc[mt][nt][2], acc[mt][nt][3]);
                const float b0 = bias[c], b1 = bias[c + 1];
                v0.x += b0; v0.y += b1; v1.x += b0; v1.y += b1;
                *(float2*)(C + (size_t)r0 * N + c)       = v0;
                *(float2*)(C + (size_t)(r0 + 8) * N + c) = v1;
            }
        }
    }
}

#define GEMM_SMEM_2T (2 * 3 * GS_TILE)   // 61440
#define GEMM_SMEM_1T (2 * 2 * GS_TILE)   // 40960

// ---------------- fp32 -> fp16 (single term) ----------------------
__global__ void cvt_f16(const float* __restrict__ src, __half* __restrict__ dst, int n4) {
    const int i = blockIdx.x * blockDim.x + threadIdx.x;
    if (i >= n4) return;
    const float4 v = ((const float4*)src)[i];
    ((__half2*)dst)[i * 2]     = __floats2half2_rn(v.x, v.y);
    ((__half2*)dst)[i * 2 + 1] = __floats2half2_rn(v.z, v.w);
}

// W [K,N] -> W^T [N,K] single fp16
__global__ void transpose_f16(const float* __restrict__ W,
                              __half* __restrict__ Wt, int K, int N) {
    __shared__ float t[32][33];
    const int n0 = blockIdx.x * 32, k0 = blockIdx.y * 32;
    const int tx = threadIdx.x;
    for (int y = threadIdx.y; y < 32; y += 8)
        t[y][tx] = W[(size_t)(k0 + y) * N + n0 + tx];
    __syncthreads();
    for (int y = threadIdx.y; y < 32; y += 8)
        Wt[(size_t)(n0 + y) * K + k0 + tx] = __float2half(t[tx][y]);
}

// ---------------- Flash attention (fp16 mma.sync) -----------------
// Q 2-term (hi/lo); K, V, P single fp16. Writes ctx single fp16.
#define FBM    128
#define FBN    64
#define FSTRIDE 208
#define FTILE  (64 * FSTRIDE)
#define FSTAGE (2 * FTILE)
#define FLASH_SMEM (2 * FSTAGE)

__global__ void __launch_bounds__(256, 1) flash_mma() {
    extern __shared__ char sm_[];
    const uint32_t sb = smem_u32(sm_);
    const int tid = threadIdx.x;
    const int wid = tid >> 5, lane = tid & 31;
    const int g = lane >> 2, tg = lane & 3;
    const int bh = blockIdx.y;
    const int b  = bh >> 4, h = bh & 15;
    const int m0 = blockIdx.x * FBM;

    const size_t tbase = (size_t)bh * N_ * DH_;

    const int qrow = m0 + wid * 16 + g;
    const char* qh = (const char*)(g_qh + tbase + (size_t)qrow * DH_);
    const char* ql = (const char*)(g_ql + tbase + (size_t)qrow * DH_);
    uint32_t qa_h[6][4], qa_l[6][4];
#pragma unroll
    for (int j = 0; j < 6; j++) {
        const int c0 = (j * 16 + tg * 2) * 2;
        qa_h[j][0] = *(const uint32_t*)(qh + c0);
        qa_h[j][1] = *(const uint32_t*)(qh + 8 * DH_ * 2 + c0);
        qa_h[j][2] = *(const uint32_t*)(qh + c0 + 16);
        qa_h[j][3] = *(const uint32_t*)(qh + 8 * DH_ * 2 + c0 + 16);
        qa_l[j][0] = *(const uint32_t*)(ql + c0);
        qa_l[j][1] = *(const uint32_t*)(ql + 8 * DH_ * 2 + c0);
        qa_l[j][2] = *(const uint32_t*)(ql + c0 + 16);
        qa_l[j][3] = *(const uint32_t*)(ql + 8 * DH_ * 2 + c0 + 16);
    }

    float oacc[12][4];
#pragma unroll
    for (int ot = 0; ot < 12; ot++)
#pragma unroll
        for (int i = 0; i < 4; i++) oacc[ot][i] = 0.f;
    float mrow0 = -1e30f, mrow1 = -1e30f, lrow0 = 0.f, lrow1 = 0.f;

    const char* srcK = (const char*)(g_kk + tbase);
    const char* srcV = (const char*)(g_vv + tbase);

    auto load_stage = [&](int s) {
        const uint32_t base = sb + (uint32_t)(s & 1) * FSTAGE;
        const int n0 = s * FBN;
#pragma unroll
        for (int i = 0; i < 6; i++) {
            const int idx = tid + i * 256;
            const int tile = idx / 768;
            const int w = idx % 768;
            const int r = w / 12, c = w % 12;
            const uint32_t so = base + (uint32_t)tile * FTILE +
                                (uint32_t)r * FSTRIDE + (uint32_t)c * 16;
            const size_t go = ((size_t)(n0 + r) * DH_ + c * 8) * 2;
            CP_ASYNC16(so, (tile == 0 ? srcK : srcV) + go);
        }
    };

    load_stage(0); CP_COMMIT();

    const int nkv = N_ / FBN;
    for (int s = 0; s < nkv; s++) {
        if (s + 1 < nkv) { load_stage(s + 1); CP_COMMIT(); CP_WAIT(1); }
        else             { CP_WAIT(0); }
        __syncthreads();

        const uint32_t kb = sb + (uint32_t)(s & 1) * FSTAGE;
        const uint32_t vb = kb + FTILE;

        float sacc[8][4];
#pragma unroll
        for (int nt = 0; nt < 8; nt++)
#pragma unroll
            for (int i = 0; i < 4; i++) sacc[nt][i] = 0.f;

#pragma unroll
        for (int j = 0; j < 6; j++) {
            uint32_t bf[8][2];
#pragma unroll
            for (int np = 0; np < 4; np++) {
                const int sel = lane >> 3;
                const uint32_t row = (uint32_t)(np * 16 + ((sel & 2) ? 8 : 0) + (lane & 7));
                const uint32_t col = (uint32_t)(j * 16 + ((sel & 1) ? 8 : 0));
                const uint32_t ad = kb + row * FSTRIDE + col * 2;
                LDMX4(bf[2*np][0], bf[2*np][1], bf[2*np+1][0], bf[2*np+1][1], ad);
            }
#pragma unroll
            for (int nt = 0; nt < 8; nt++) {
                mma_f16(sacc[nt], qa_h[j], bf[nt]);
                mma_f16(sacc[nt], qa_l[j], bf[nt]);
            }
        }

        float mx0 = -1e30f, mx1 = -1e30f;
#pragma unroll
        for (int nt = 0; nt < 8; nt++) {
            mx0 = fmaxf(mx0, fmaxf(sacc[nt][0], sacc[nt][1]));
            mx1 = fmaxf(mx1, fmaxf(sacc[nt][2], sacc[nt][3]));
        }
        mx0 = fmaxf(mx0, __shfl_xor_sync(0xffffffffu, mx0, 1));
        mx0 = fmaxf(mx0, __shfl_xor_sync(0xffffffffu, mx0, 2));
        mx1 = fmaxf(mx1, __shfl_xor_sync(0xffffffffu, mx1, 1));
        mx1 = fmaxf(mx1, __shfl_xor_sync(0xffffffffu, mx1, 2));

        const float mn0 = fmaxf(mrow0, mx0), mn1 = fmaxf(mrow1, mx1);
        const float corr0 = __expf(mrow0 - mn0), corr1 = __expf(mrow1 - mn1);
        mrow0 = mn0; mrow1 = mn1;

        float sum0 = 0.f, sum1 = 0.f;
#pragma unroll
        for (int nt = 0; nt < 8; nt++) {
            sacc[nt][0] = __expf(sacc[nt][0] - mn0);
            sacc[nt][1] = __expf(sacc[nt][1] - mn0);
            sacc[nt][2] = __expf(sacc[nt][2] - mn1);
            sacc[nt][3] = __expf(sacc[nt][3] - mn1);
            sum0 += sacc[nt][0] + sacc[nt][1];
            sum1 += sacc[nt][2] + sacc[nt][3];
        }
        lrow0 = lrow0 * corr0 + sum0;
        lrow1 = lrow1 * corr1 + sum1;
#pragma unroll
        for (int ot = 0; ot < 12; ot++) {
            oacc[ot][0] *= corr0; oacc[ot][1] *= corr0;
            oacc[ot][2] *= corr1; oacc[ot][3] *= corr1;
        }

        // ---- O += P V (P single fp16) ----
#pragma unroll
        for (int jj = 0; jj < 4; jj++) {
            uint32_t pa[4];
            pa[0] = pk_h2(sacc[2*jj][0],   sacc[2*jj][1]);
            pa[1] = pk_h2(sacc[2*jj][2],   sacc[2*jj][3]);
            pa[2] = pk_h2(sacc[2*jj+1][0], sacc[2*jj+1][1]);
            pa[3] = pk_h2(sacc[2*jj+1][2], sacc[2*jj+1][3]);
#pragma unroll
            for (int np = 0; np < 6; np++) {
                uint32_t vf[2][2];
                const int sel = lane >> 3;
                const uint32_t row = (uint32_t)(jj * 16 + ((sel & 1) ? 8 : 0) + (lane & 7));
                const uint32_t col = (uint32_t)(np * 16 + ((sel & 2) ? 8 : 0));
                const uint32_t ad = vb + row * FSTRIDE + col * 2;
                LDMX4T(vf[0][0], vf[0][1], vf[1][0], vf[1][1], ad);
                mma_f16(oacc[2*np],   pa, vf[0]);
                mma_f16(oacc[2*np+1], pa, vf[1]);
            }
        }
        __syncthreads();
    }

    lrow0 += __shfl_xor_sync(0xffffffffu, lrow0, 1);
    lrow0 += __shfl_xor_sync(0xffffffffu, lrow0, 2);
    lrow1 += __shfl_xor_sync(0xffffffffu, lrow1, 1);
    lrow1 += __shfl_xor_sync(0xffffffffu, lrow1, 2);
    const float inv0 = 1.f / lrow0, inv1 = 1.f / lrow1;

    const int nrow = m0 + wid * 16 + g;
    const size_t ob0 = (size_t)(b * N_ + nrow) * HDH + h * DH_;
    const size_t ob1 = (size_t)(b * N_ + nrow + 8) * HDH + h * DH_;
#pragma unroll
    for (int ot = 0; ot < 12; ot++) {
        const int d0 = ot * 8 + tg * 2;
        *(__half2*)(g_chi + ob0 + d0) =
            __floats2half2_rn(oacc[ot][0] * inv0, oacc[ot][1] * inv0);
        *(__half2*)(g_chi + ob1 + d0) =
            __floats2half2_rn(oacc[ot][2] * inv1, oacc[ot][3] * inv1);
    }
}

// ------------------------------------------------------------------
extern "C" void kernel_launch(void* const* d_in, const int* in_sizes, int n_in,
                              void* d_out, int out_size) {
    const float* x    = (const float*)d_in[0];
    const float* f1   = (const float*)d_in[1];
    const float* f2   = (const float*)d_in[2];
    const float* f3   = (const float*)d_in[3];
    const float* Wqkv = (const float*)d_in[4];
    const float* Wout = (const float*)d_in[5];
    const float* bout = (const float*)d_in[6];
    float* out = (float*)d_out;

    __half *xh, *chi, *wqt, *wot;
    cudaGetSymbolAddress((void**)&xh,  g_xh);
    cudaGetSymbolAddress((void**)&chi, g_chi);
    cudaGetSymbolAddress((void**)&wqt, g_wqt);
    cudaGetSymbolAddress((void**)&wot, g_wot);

    cudaFuncSetAttribute((const void*)gemm_mma<1, 1>,
                         cudaFuncAttributeMaxDynamicSharedMemorySize, GEMM_SMEM_1T);
    cudaFuncSetAttribute((const void*)gemm_mma<0, 1>,
                         cudaFuncAttributeMaxDynamicSharedMemorySize, GEMM_SMEM_1T);
    cudaFuncSetAttribute((const void*)flash_mma,
                         cudaFuncAttributeMaxDynamicSharedMemorySize, FLASH_SMEM);

    // 0) cos/sin table
    cs_init<<<(3 * N_ * 32 + 255) / 256, 256>>>(f1, f2, f3);

    // 1) x -> fp16; weights -> transposed fp16
    cvt_f16<<<(M_ * DIM_ / 4 + 255) / 256, 256>>>(x, xh, M_ * DIM_ / 4);
    transpose_f16<<<dim3(QKV3 / 32, DIM_ / 32), dim3(32, 8)>>>(Wqkv, wqt, DIM_, QKV3);
    transpose_f16<<<dim3(HDH / 32, HDH / 32), dim3(32, 8)>>>(Wout, wot, HDH, HDH);

    // 2) QKV GEMM (1-term) with fused RoPE + head-transpose epilogue
    gemm_mma<1, 1><<<dim3(QKV3 / 128, M_ / 128), 256, GEMM_SMEM_1T>>>(
        xh, nullptr, wqt, nullptr, nullptr, QKV3, DIM_);

    // 3) Flash attention (writes ctx single fp16)
    flash_mma<<<dim3(N_ / FBM, B_ * H_), 256, FLASH_SMEM>>>();

    // 4) Output GEMM (1-term) + bias
    gemm_mma<0, 1><<<dim3(HDH / 128, M_ / 128), 256, GEMM_SMEM_1T>>>(
        chi, nullptr, wot, bout, out, HDH, HDH);
}

// round 15
// speedup vs baseline: 1.6785x; 1.1212x over previous
#include <cuda_runtime.h>
#include <cuda_fp16.h>
#include <cstdint>

#define B_    4
#define N_    2048
#define DIM_  1536
#define H_    16
#define DH_   96
#define QKV3  4608      // 3*H*DH
#define HDH   1536      // H*DH
#define M_    (B_*N_)   // 8192
#define SCALE_ 0.10206207261596575f  // 96^-0.5

// ---------------- scratch (no allocations allowed) ----------------
__device__ __half g_xh [(size_t)M_ * DIM_];
__device__ __half g_chi[(size_t)M_ * HDH];
__device__ __half g_wqt[(size_t)QKV3 * DIM_];        // W^T [N,K] single fp16
__device__ __half g_wot[(size_t)HDH * HDH];

// q, k, v single fp16. layout [b*H + h][n][d]; q pre-scaled
#define PER_T ((size_t)B_ * H_ * N_ * DH_)
__device__ __half g_qh[PER_T];
__device__ __half g_kk[PER_T];
__device__ __half g_vv[PER_T];

// cos/sin table: [chunk(3)][n(2048)][j(32)] -> (cos f, sin f)
__device__ float2 g_cs[3 * N_ * 32];

// ================= helpers (sm_80+ only) ==========================
__device__ __forceinline__ uint32_t smem_u32(const void* p) {
    uint32_t a;
    asm("{ .reg .u64 t; cvta.to.shared.u64 t, %1; cvt.u32.u64 %0, t; }"
        : "=r"(a) : "l"(p));
    return a;
}
#define CP_ASYNC16(saddr, gptr) \
    asm volatile("cp.async.cg.shared.global [%0], [%1], 16;" :: "r"(saddr), "l"(gptr))
#define CP_COMMIT() asm volatile("cp.async.commit_group;" ::: "memory")
#define CP_WAIT(n)  asm volatile("cp.async.wait_group %0;" :: "n"(n) : "memory")

#define LDMX4(r0,r1,r2,r3,addr) \
    asm volatile("ldmatrix.sync.aligned.m8n8.x4.shared.b16 {%0,%1,%2,%3}, [%4];" \
        : "=r"(r0),"=r"(r1),"=r"(r2),"=r"(r3) : "r"(addr))
#define LDMX4T(r0,r1,r2,r3,addr) \
    asm volatile("ldmatrix.sync.aligned.m8n8.x4.trans.shared.b16 {%0,%1,%2,%3}, [%4];" \
        : "=r"(r0),"=r"(r1),"=r"(r2),"=r"(r3) : "r"(addr))

__device__ __forceinline__ void mma_f16(float* c, const uint32_t* a, const uint32_t* b) {
    asm volatile(
        "mma.sync.aligned.m16n8k16.row.col.f32.f16.f16.f32 "
        "{%0,%1,%2,%3}, {%4,%5,%6,%7}, {%8,%9}, {%0,%1,%2,%3};"
        : "+f"(c[0]), "+f"(c[1]), "+f"(c[2]), "+f"(c[3])
        : "r"(a[0]), "r"(a[1]), "r"(a[2]), "r"(a[3]), "r"(b[0]), "r"(b[1]));
}
__device__ __forceinline__ uint32_t pk_h2(float a, float b) {
    __half2 t = __floats2half2_rn(a, b);
    return *(uint32_t*)&t;
}

// ---- cos/sin table init --------------------------------------------
__global__ void cs_init(const float* __restrict__ f1, const float* __restrict__ f2,
                        const float* __restrict__ f3) {
    const int i = blockIdx.x * 256 + threadIdx.x;
    if (i >= 3 * N_ * 32) return;
    const int chunk = i / (N_ * 32);
    const int rem = i - chunk * (N_ * 32);
    const float* f = (chunk == 0) ? f1 : ((chunk == 1) ? f2 : f3);
    const float fr = f[rem];
    g_cs[i] = make_float2(cosf(fr), sinf(fr));
}

// ====== fp16 mma.sync GEMM (single activation term) ===============
// ROPE=0: C = A@Wt^T + bias (fp32 out).
// ROPE=1: QKV gemm; epilogue applies RoPE + head transpose, writes
//         g_qh (scaled), g_kk, g_vv fp16 directly.
#define GS_STRIDE 80
#define GS_TILE   10240
#define GEMM_SMEM (2 * 2 * GS_TILE)   // 40960

template <int ROPE>
__global__ void __launch_bounds__(256, 2)
gemm_mma(const __half* __restrict__ A, const __half* __restrict__ Wt,
         const float* __restrict__ bias, float* __restrict__ C, int N, int K) {
    extern __shared__ char sm_[];
    const uint32_t sb = smem_u32(sm_);
    const int tid = threadIdx.x;
    const int wid = tid >> 5, lane = tid & 31;
    const int g = lane >> 2, tg = lane & 3;
    const int wm = wid & 3, wn = wid >> 2;
    const int brow = blockIdx.y * 128;
    const int bcol = blockIdx.x * 128;

    const uint32_t STAGE = 2 * GS_TILE;

    const int lane7 = lane & 7, sel = lane >> 3;
    const uint32_t a_rowadd = (uint32_t)(lane7 + ((sel & 1) ? 8 : 0));
    const uint32_t a_colb   = (uint32_t)(((sel >> 1) ? 8 : 0) * 2);
    const uint32_t b_rowadd = (uint32_t)(lane7 + ((sel & 2) ? 8 : 0));
    const uint32_t b_colb   = (uint32_t)(((sel & 1) ? 8 : 0) * 2);

    float acc[2][8][4];
#pragma unroll
    for (int mt = 0; mt < 2; mt++)
#pragma unroll
        for (int nt = 0; nt < 8; nt++)
#pragma unroll
            for (int i = 0; i < 4; i++) acc[mt][nt][i] = 0.f;

    const int nst = K / 32;

    auto load_stage = [&](int s) {
        const uint32_t base = sb + (uint32_t)(s & 1) * STAGE;
        const int k0 = s * 32;
#pragma unroll
        for (int i = 0; i < 4; i++) {
            const int idx = tid + i * 256;
            const int tile = idx >> 9;           // 0..1
            const int w = idx & 511;
            const int r = w >> 2, c = w & 3;
            const uint32_t so = base + (uint32_t)tile * GS_TILE +
                                (uint32_t)r * GS_STRIDE + (uint32_t)c * 16;
            const char* gp;
            if (tile == 0) gp = (const char*)A  + ((size_t)(brow + r) * K + k0 + c * 8) * 2;
            else           gp = (const char*)Wt + ((size_t)(bcol + r) * K + k0 + c * 8) * 2;
            CP_ASYNC16(so, gp);
        }
    };

    load_stage(0); CP_COMMIT();

    for (int s = 0; s < nst; s++) {
        if (s + 1 < nst) { load_stage(s + 1); CP_COMMIT(); CP_WAIT(1); }
        else             { CP_WAIT(0); }
        __syncthreads();

        const uint32_t base = sb + (uint32_t)(s & 1) * STAGE;
#pragma unroll
        for (int kk = 0; kk < 2; kk++) {
            const uint32_t kb = (uint32_t)(kk * 16) * 2;
            uint32_t ah[2][4], bw[8][2];
#pragma unroll
            for (int mt = 0; mt < 2; mt++) {
                const uint32_t ar = base + (uint32_t)(wm * 32 + mt * 16 + a_rowadd) * GS_STRIDE
                                  + kb + a_colb;
                LDMX4(ah[mt][0], ah[mt][1], ah[mt][2], ah[mt][3], ar);
            }
#pragma unroll
            for (int nb = 0; nb < 4; nb++) {
                const uint32_t br = base + GS_TILE
                                  + (uint32_t)(wn * 64 + nb * 16 + b_rowadd) * GS_STRIDE
                                  + kb + b_colb;
                LDMX4(bw[2*nb][0], bw[2*nb][1], bw[2*nb+1][0], bw[2*nb+1][1], br);
            }
#pragma unroll
            for (int mt = 0; mt < 2; mt++)
#pragma unroll
                for (int nt = 0; nt < 8; nt++)
                    mma_f16(acc[mt][nt], ah[mt], bw[nt]);
        }
        __syncthreads();
    }

    if (ROPE) {
        const int which = bcol / HDH;   // 0=q 1=k 2=v
#pragma unroll
        for (int mt = 0; mt < 2; mt++) {
#pragma unroll
            for (int hf = 0; hf < 2; hf++) {
                const int row = brow + wm * 32 + mt * 16 + g + hf * 8;
                const int bb = row >> 11, n = row & (N_ - 1);
                const int i0 = hf * 2;
#pragma unroll
                for (int pp = 0; pp < 4; pp++) {
                    const int ntA = (pp >> 1) * 4 + (pp & 1);
                    const int ntB = ntA + 2;
                    const int cA = bcol + wn * 64 + ntA * 8 + tg * 2;
                    const int cq = cA - which * HDH;
                    const int hh = cq / DH_;
                    const int dA = cq - hh * DH_;
                    const int jA = dA & 31;
                    const int chunk = dA >> 5;
                    const float a0 = acc[mt][ntA][i0], a1 = acc[mt][ntA][i0 + 1];
                    const float b0 = acc[mt][ntB][i0], b1 = acc[mt][ntB][i0 + 1];
                    float oA0, oA1, oB0, oB1;
                    if (which == 2) {
                        oA0 = a0; oA1 = a1; oB0 = b0; oB1 = b1;
                    } else {
                        const float2* csp = g_cs + (size_t)(chunk * N_ + n) * 32;
                        const float2 cA0 = csp[jA],      cA1 = csp[jA + 1];
                        const float2 cB0 = csp[jA + 16], cB1 = csp[jA + 17];
                        oA0 = a0 * cA0.x - b0 * cA0.y;
                        oA1 = a1 * cA1.x - b1 * cA1.y;
                        oB0 = b0 * cB0.x + a0 * cB0.y;
                        oB1 = b1 * cB1.x + a1 * cB1.y;
                        if (which == 0) {
                            oA0 *= SCALE_; oA1 *= SCALE_; oB0 *= SCALE_; oB1 *= SCALE_;
                        }
                    }
                    const size_t oA = ((size_t)((bb * H_ + hh) * N_ + n)) * DH_ + dA;
                    const size_t oB = oA + 16;
                    __half* dst = (which == 0) ? g_qh : ((which == 1) ? g_kk : g_vv);
                    *(__half2*)(dst + oA) = __floats2half2_rn(oA0, oA1);
                    *(__half2*)(dst + oB) = __floats2half2_rn(oB0, oB1);
                }
            }
        }
    } else {
#pragma unroll
        for (int mt = 0; mt < 2; mt++) {
            const int r0 = brow + wm * 32 + mt * 16 + g;
#pragma unroll
            for (int nt = 0; nt < 8; nt++) {
                const int c = bcol + wn * 64 + nt * 8 + tg * 2;
                float2 v0 = make_float2(acc[mt][nt][0], acc[mt][nt][1]);
                float2 v1 = make_float2(acc[mt][nt][2], acc[mt][nt][3]);
                const float b0 = bias[c], b1 = bias[c + 1];
                v0.x += b0; v0.y += b1; v1.x += b0; v1.y += b1;
                *(float2*)(C + (size_t)r0 * N + c)       = v0;
                *(float2*)(C + (size_t)(r0 + 8) * N + c) = v1;
            }
        }
    }
}

// ---------------- fp32 -> fp16 ------------------------------------
__global__ void cvt_f16(const float* __restrict__ src, __half* __restrict__ dst, int n4) {
    const int i = blockIdx.x * blockDim.x + threadIdx.x;
    if (i >= n4) return;
    const float4 v = ((const float4*)src)[i];
    ((__half2*)dst)[i * 2]     = __floats2half2_rn(v.x, v.y);
    ((__half2*)dst)[i * 2 + 1] = __floats2half2_rn(v.z, v.w);
}

// W [K,N] -> W^T [N,K] single fp16
__global__ void transpose_f16(const float* __restrict__ W,
                              __half* __restrict__ Wt, int K, int N) {
    __shared__ float t[32][33];
    const int n0 = blockIdx.x * 32, k0 = blockIdx.y * 32;
    const int tx = threadIdx.x;
    for (int y = threadIdx.y; y < 32; y += 8)
        t[y][tx] = W[(size_t)(k0 + y) * N + n0 + tx];
    __syncthreads();
    for (int y = threadIdx.y; y < 32; y += 8)
        Wt[(size_t)(n0 + y) * K + k0 + tx] = __float2half(t[tx][y]);
}

// ---------------- Flash attention (fp16 mma.sync) -----------------
// Q, K, V, P all single fp16. Writes ctx single fp16.
#define FBM    128
#define FBN    64
#define FSTRIDE 208
#define FTILE  (64 * FSTRIDE)
#define FSTAGE (2 * FTILE)
#define FLASH_SMEM (2 * FSTAGE)

__global__ void __launch_bounds__(256, 1) flash_mma() {
    extern __shared__ char sm_[];
    const uint32_t sb = smem_u32(sm_);
    const int tid = threadIdx.x;
    const int wid = tid >> 5, lane = tid & 31;
    const int g = lane >> 2, tg = lane & 3;
    const int bh = blockIdx.y;
    const int b  = bh >> 4, h = bh & 15;
    const int m0 = blockIdx.x * FBM;

    const size_t tbase = (size_t)bh * N_ * DH_;

    const int qrow = m0 + wid * 16 + g;
    const char* qh = (const char*)(g_qh + tbase + (size_t)qrow * DH_);
    uint32_t qa[6][4];
#pragma unroll
    for (int j = 0; j < 6; j++) {
        const int c0 = (j * 16 + tg * 2) * 2;
        qa[j][0] = *(const uint32_t*)(qh + c0);
        qa[j][1] = *(const uint32_t*)(qh + 8 * DH_ * 2 + c0);
        qa[j][2] = *(const uint32_t*)(qh + c0 + 16);
        qa[j][3] = *(const uint32_t*)(qh + 8 * DH_ * 2 + c0 + 16);
    }

    float oacc[12][4];
#pragma unroll
    for (int ot = 0; ot < 12; ot++)
#pragma unroll
        for (int i = 0; i < 4; i++) oacc[ot][i] = 0.f;
    float mrow0 = -1e30f, mrow1 = -1e30f, lrow0 = 0.f, lrow1 = 0.f;

    const char* srcK = (const char*)(g_kk + tbase);
    const char* srcV = (const char*)(g_vv + tbase);

    auto load_stage = [&](int s) {
        const uint32_t base = sb + (uint32_t)(s & 1) * FSTAGE;
        const int n0 = s * FBN;
#pragma unroll
        for (int i = 0; i < 6; i++) {
            const int idx = tid + i * 256;
            const int tile = idx / 768;
            const int w = idx % 768;
            const int r = w / 12, c = w % 12;
            const uint32_t so = base + (uint32_t)tile * FTILE +
                                (uint32_t)r * FSTRIDE + (uint32_t)c * 16;
            const size_t go = ((size_t)(n0 + r) * DH_ + c * 8) * 2;
            CP_ASYNC16(so, (tile == 0 ? srcK : srcV) + go);
        }
    };

    load_stage(0); CP_COMMIT();

    const int nkv = N_ / FBN;
    for (int s = 0; s < nkv; s++) {
        if (s + 1 < nkv) { load_stage(s + 1); CP_COMMIT(); CP_WAIT(1); }
        else             { CP_WAIT(0); }
        __syncthreads();

        const uint32_t kb = sb + (uint32_t)(s & 1) * FSTAGE;
        const uint32_t vb = kb + FTILE;

        float sacc[8][4];
#pragma unroll
        for (int nt = 0; nt < 8; nt++)
#pragma unroll
            for (int i = 0; i < 4; i++) sacc[nt][i] = 0.f;

#pragma unroll
        for (int j = 0; j < 6; j++) {
            uint32_t bf[8][2];
#pragma unroll
            for (int np = 0; np < 4; np++) {
                const int sel = lane >> 3;
                const uint32_t row = (uint32_t)(np * 16 + ((sel & 2) ? 8 : 0) + (lane & 7));
                const uint32_t col = (uint32_t)(j * 16 + ((sel & 1) ? 8 : 0));
                const uint32_t ad = kb + row * FSTRIDE + col * 2;
                LDMX4(bf[2*np][0], bf[2*np][1], bf[2*np+1][0], bf[2*np+1][1], ad);
            }
#pragma unroll
            for (int nt = 0; nt < 8; nt++)
                mma_f16(sacc[nt], qa[j], bf[nt]);
        }

        float mx0 = -1e30f, mx1 = -1e30f;
#pragma unroll
        for (int nt = 0; nt < 8; nt++) {
            mx0 = fmaxf(mx0, fmaxf(sacc[nt][0], sacc[nt][1]));
            mx1 = fmaxf(mx1, fmaxf(sacc[nt][2], sacc[nt][3]));
        }
        mx0 = fmaxf(mx0, __shfl_xor_sync(0xffffffffu, mx0, 1));
        mx0 = fmaxf(mx0, __shfl_xor_sync(0xffffffffu, mx0, 2));
        mx1 = fmaxf(mx1, __shfl_xor_sync(0xffffffffu, mx1, 1));
        mx1 = fmaxf(mx1, __shfl_xor_sync(0xffffffffu, mx1, 2));

        const float mn0 = fmaxf(mrow0, mx0), mn1 = fmaxf(mrow1, mx1);
        const float corr0 = __expf(mrow0 - mn0), corr1 = __expf(mrow1 - mn1);
        mrow0 = mn0; mrow1 = mn1;

        float sum0 = 0.f, sum1 = 0.f;
#pragma unroll
        for (int nt = 0; nt < 8; nt++) {
            sacc[nt][0] = __expf(sacc[nt][0] - mn0);
            sacc[nt][1] = __expf(sacc[nt][1] - mn0);
            sacc[nt][2] = __expf(sacc[nt][2] - mn1);
            sacc[nt][3] = __expf(sacc[nt][3] - mn1);
            sum0 += sacc[nt][0] + sacc[nt][1];
            sum1 += sacc[nt][2] + sacc[nt][3];
        }
        lrow0 = lrow0 * corr0 + sum0;
        lrow1 = lrow1 * corr1 + sum1;
#pragma unroll
        for (int ot = 0; ot < 12; ot++) {
            oacc[ot][0] *= corr0; oacc[ot][1] *= corr0;
            oacc[ot][2] *= corr1; oacc[ot][3] *= corr1;
        }

        // ---- O += P V (P single fp16) ----
#pragma unroll
        for (int jj = 0; jj < 4; jj++) {
            uint32_t pa[4];
            pa[0] = pk_h2(sacc[2*jj][0],   sacc[2*jj][1]);
            pa[1] = pk_h2(sacc[2*jj][2],   sacc[2*jj][3]);
            pa[2] = pk_h2(sacc[2*jj+1][0], sacc[2*jj+1][1]);
            pa[3] = pk_h2(sacc[2*jj+1][2], sacc[2*jj+1][3]);
#pragma unroll
            for (int np = 0; np < 6; np++) {
                uint32_t vf[2][2];
                const int sel = lane >> 3;
                const uint32_t row = (uint32_t)(jj * 16 + ((sel & 1) ? 8 : 0) + (lane & 7));
                const uint32_t col = (uint32_t)(np * 16 + ((sel & 2) ? 8 : 0));
                const uint32_t ad = vb + row * FSTRIDE + col * 2;
                LDMX4T(vf[0][0], vf[0][1], vf[1][0], vf[1][1], ad);
                mma_f16(oacc[2*np],   pa, vf[0]);
                mma_f16(oacc[2*np+1], pa, vf[1]);
            }
        }
        __syncthreads();
    }

    lrow0 += __shfl_xor_sync(0xffffffffu, lrow0, 1);
    lrow0 += __shfl_xor_sync(0xffffffffu, lrow0, 2);
    lrow1 += __shfl_xor_sync(0xffffffffu, lrow1, 1);
    lrow1 += __shfl_xor_sync(0xffffffffu, lrow1, 2);
    const float inv0 = 1.f / lrow0, inv1 = 1.f / lrow1;

    const int nrow = m0 + wid * 16 + g;
    const size_t ob0 = (size_t)(b * N_ + nrow) * HDH + h * DH_;
    const size_t ob1 = (size_t)(b * N_ + nrow + 8) * HDH + h * DH_;
#pragma unroll
    for (int ot = 0; ot < 12; ot++) {
        const int d0 = ot * 8 + tg * 2;
        *(__half2*)(g_chi + ob0 + d0) =
            __floats2half2_rn(oacc[ot][0] * inv0, oacc[ot][1] * inv0);
        *(__half2*)(g_chi + ob1 + d0) =
            __floats2half2_rn(oacc[ot][2] * inv1, oacc[ot][3] * inv1);
    }
}

// ------------------------------------------------------------------
extern "C" void kernel_launch(void* const* d_in, const int* in_sizes, int n_in,
                              void* d_out, int out_size) {
    const float* x    = (const float*)d_in[0];
    const float* f1   = (const float*)d_in[1];
    const float* f2   = (const float*)d_in[2];
    const float* f3   = (const float*)d_in[3];
    const float* Wqkv = (const float*)d_in[4];
    const float* Wout = (const float*)d_in[5];
    const float* bout = (const float*)d_in[6];
    float* out = (float*)d_out;

    __half *xh, *chi, *wqt, *wot;
    cudaGetSymbolAddress((void**)&xh,  g_xh);
    cudaGetSymbolAddress((void**)&chi, g_chi);
    cudaGetSymbolAddress((void**)&wqt, g_wqt);
    cudaGetSymbolAddress((void**)&wot, g_wot);

    cudaFuncSetAttribute((const void*)gemm_mma<1>,
                         cudaFuncAttributeMaxDynamicSharedMemorySize, GEMM_SMEM);
    cudaFuncSetAttribute((const void*)gemm_mma<0>,
                         cudaFuncAttributeMaxDynamicSharedMemorySize, GEMM_SMEM);
    cudaFuncSetAttribute((const void*)flash_mma,
                         cudaFuncAttributeMaxDynamicSharedMemorySize, FLASH_SMEM);

    // 0) cos/sin table
    cs_init<<<(3 * N_ * 32 + 255) / 256, 256>>>(f1, f2, f3);

    // 1) x -> fp16; weights -> transposed fp16
    cvt_f16<<<(M_ * DIM_ / 4 + 255) / 256, 256>>>(x, xh, M_ * DIM_ / 4);
    transpose_f16<<<dim3(QKV3 / 32, DIM_ / 32), dim3(32, 8)>>>(Wqkv, wqt, DIM_, QKV3);
    transpose_f16<<<dim3(HDH / 32, HDH / 32), dim3(32, 8)>>>(Wout, wot, HDH, HDH);

    // 2) QKV GEMM with fused RoPE + head-transpose epilogue
    gemm_mma<1><<<dim3(QKV3 / 128, M_ / 128), 256, GEMM_SMEM>>>(
        xh, wqt, nullptr, nullptr, QKV3, DIM_);

    // 3) Flash attention (writes ctx single fp16)
    flash_mma<<<dim3(N_ / FBM, B_ * H_), 256, FLASH_SMEM>>>();

    // 4) Output GEMM + bias
    gemm_mma<0><<<dim3(HDH / 128, M_ / 128), 256, GEMM_SMEM>>>(
        chi, wot, bout, out, HDH, HDH);
}

// round 16
// speedup vs baseline: 1.7429x; 1.0384x over previous
#include <cuda_runtime.h>
#include <cuda_fp16.h>
#include <cstdint>

#define B_    4
#define N_    2048
#define DIM_  1536
#define H_    16
#define DH_   96
#define QKV3  4608      // 3*H*DH
#define HDH   1536      // H*DH
#define M_    (B_*N_)   // 8192
#define SCALE_ 0.10206207261596575f  // 96^-0.5

// ---------------- scratch (no allocations allowed) ----------------
__device__ __half g_xh [(size_t)M_ * DIM_];
__device__ __half g_chi[(size_t)M_ * HDH];
__device__ __half g_wqt[(size_t)QKV3 * DIM_];        // W^T [N,K] single fp16
__device__ __half g_wot[(size_t)HDH * HDH];

// q, k, v single fp16. layout [b*H + h][n][d]; q pre-scaled
#define PER_T ((size_t)B_ * H_ * N_ * DH_)
__device__ __half g_qh[PER_T];
__device__ __half g_kk[PER_T];
__device__ __half g_vv[PER_T];

// cos/sin table: [chunk(3)][n(2048)][j(32)] -> (cos f, sin f)
__device__ float2 g_cs[3 * N_ * 32];

// ================= helpers (sm_80+ only) ==========================
__device__ __forceinline__ uint32_t smem_u32(const void* p) {
    uint32_t a;
    asm("{ .reg .u64 t; cvta.to.shared.u64 t, %1; cvt.u32.u64 %0, t; }"
        : "=r"(a) : "l"(p));
    return a;
}
#define CP_ASYNC16(saddr, gptr) \
    asm volatile("cp.async.cg.shared.global [%0], [%1], 16;" :: "r"(saddr), "l"(gptr))
#define CP_COMMIT() asm volatile("cp.async.commit_group;" ::: "memory")
#define CP_WAIT(n)  asm volatile("cp.async.wait_group %0;" :: "n"(n) : "memory")

#define LDMX4(r0,r1,r2,r3,addr) \
    asm volatile("ldmatrix.sync.aligned.m8n8.x4.shared.b16 {%0,%1,%2,%3}, [%4];" \
        : "=r"(r0),"=r"(r1),"=r"(r2),"=r"(r3) : "r"(addr))
#define LDMX4T(r0,r1,r2,r3,addr) \
    asm volatile("ldmatrix.sync.aligned.m8n8.x4.trans.shared.b16 {%0,%1,%2,%3}, [%4];" \
        : "=r"(r0),"=r"(r1),"=r"(r2),"=r"(r3) : "r"(addr))

__device__ __forceinline__ void mma_f16(float* c, const uint32_t* a, const uint32_t* b) {
    asm volatile(
        "mma.sync.aligned.m16n8k16.row.col.f32.f16.f16.f32 "
        "{%0,%1,%2,%3}, {%4,%5,%6,%7}, {%8,%9}, {%0,%1,%2,%3};"
        : "+f"(c[0]), "+f"(c[1]), "+f"(c[2]), "+f"(c[3])
        : "r"(a[0]), "r"(a[1]), "r"(a[2]), "r"(a[3]), "r"(b[0]), "r"(b[1]));
}
__device__ __forceinline__ uint32_t pk_h2(float a, float b) {
    __half2 t = __floats2half2_rn(a, b);
    return *(uint32_t*)&t;
}

// ---- cos/sin table init --------------------------------------------
__global__ void cs_init(const float* __restrict__ f1, const float* __restrict__ f2,
                        const float* __restrict__ f3) {
    const int i = blockIdx.x * 256 + threadIdx.x;
    if (i >= 3 * N_ * 32) return;
    const int chunk = i / (N_ * 32);
    const int rem = i - chunk * (N_ * 32);
    const float* f = (chunk == 0) ? f1 : ((chunk == 1) ? f2 : f3);
    const float fr = f[rem];
    g_cs[i] = make_float2(cosf(fr), sinf(fr));
}

// ====== fp16 mma.sync GEMM (single activation term) ===============
// ROPE=0: C = A@Wt^T + bias (fp32 out).
// ROPE=1: QKV gemm; epilogue applies RoPE + head transpose, writes
//         g_qh (scaled), g_kk, g_vv fp16 directly.
#define GS_STRIDE 80
#define GS_TILE   10240
#define GEMM_SMEM (2 * 2 * GS_TILE)   // 40960

template <int ROPE>
__global__ void __launch_bounds__(256, 2)
gemm_mma(const __half* __restrict__ A, const __half* __restrict__ Wt,
         const float* __restrict__ bias, float* __restrict__ C, int N, int K) {
    extern __shared__ char sm_[];
    const uint32_t sb = smem_u32(sm_);
    const int tid = threadIdx.x;
    const int wid = tid >> 5, lane = tid & 31;
    const int g = lane >> 2, tg = lane & 3;
    const int wm = wid & 3, wn = wid >> 2;
    const int brow = blockIdx.y * 128;
    const int bcol = blockIdx.x * 128;

    const uint32_t STAGE = 2 * GS_TILE;

    const int lane7 = lane & 7, sel = lane >> 3;
    const uint32_t a_rowadd = (uint32_t)(lane7 + ((sel & 1) ? 8 : 0));
    const uint32_t a_colb   = (uint32_t)(((sel >> 1) ? 8 : 0) * 2);
    const uint32_t b_rowadd = (uint32_t)(lane7 + ((sel & 2) ? 8 : 0));
    const uint32_t b_colb   = (uint32_t)(((sel & 1) ? 8 : 0) * 2);

    float acc[2][8][4];
#pragma unroll
    for (int mt = 0; mt < 2; mt++)
#pragma unroll
        for (int nt = 0; nt < 8; nt++)
#pragma unroll
            for (int i = 0; i < 4; i++) acc[mt][nt][i] = 0.f;

    const int nst = K / 32;

    auto load_stage = [&](int s) {
        const uint32_t base = sb + (uint32_t)(s & 1) * STAGE;
        const int k0 = s * 32;
#pragma unroll
        for (int i = 0; i < 4; i++) {
            const int idx = tid + i * 256;
            const int tile = idx >> 9;           // 0..1
            const int w = idx & 511;
            const int r = w >> 2, c = w & 3;
            const uint32_t so = base + (uint32_t)tile * GS_TILE +
                                (uint32_t)r * GS_STRIDE + (uint32_t)c * 16;
            const char* gp;
            if (tile == 0) gp = (const char*)A  + ((size_t)(brow + r) * K + k0 + c * 8) * 2;
            else           gp = (const char*)Wt + ((size_t)(bcol + r) * K + k0 + c * 8) * 2;
            CP_ASYNC16(so, gp);
        }
    };

    load_stage(0); CP_COMMIT();

    for (int s = 0; s < nst; s++) {
        if (s + 1 < nst) { load_stage(s + 1); CP_COMMIT(); CP_WAIT(1); }
        else             { CP_WAIT(0); }
        __syncthreads();

        const uint32_t base = sb + (uint32_t)(s & 1) * STAGE;
#pragma unroll
        for (int kk = 0; kk < 2; kk++) {
            const uint32_t kb = (uint32_t)(kk * 16) * 2;
            uint32_t ah[2][4], bw[8][2];
#pragma unroll
            for (int mt = 0; mt < 2; mt++) {
                const uint32_t ar = base + (uint32_t)(wm * 32 + mt * 16 + a_rowadd) * GS_STRIDE
                                  + kb + a_colb;
                LDMX4(ah[mt][0], ah[mt][1], ah[mt][2], ah[mt][3], ar);
            }
#pragma unroll
            for (int nb = 0; nb < 4; nb++) {
                const uint32_t br = base + GS_TILE
                                  + (uint32_t)(wn * 64 + nb * 16 + b_rowadd) * GS_STRIDE
                                  + kb + b_colb;
                LDMX4(bw[2*nb][0], bw[2*nb][1], bw[2*nb+1][0], bw[2*nb+1][1], br);
            }
#pragma unroll
            for (int mt = 0; mt < 2; mt++)
#pragma unroll
                for (int nt = 0; nt < 8; nt++)
                    mma_f16(acc[mt][nt], ah[mt], bw[nt]);
        }
        __syncthreads();
    }

    if (ROPE) {
        const int which = bcol / HDH;   // 0=q 1=k 2=v
#pragma unroll
        for (int mt = 0; mt < 2; mt++) {
#pragma unroll
            for (int hf = 0; hf < 2; hf++) {
                const int row = brow + wm * 32 + mt * 16 + g + hf * 8;
                const int bb = row >> 11, n = row & (N_ - 1);
                const int i0 = hf * 2;
#pragma unroll
                for (int pp = 0; pp < 4; pp++) {
                    const int ntA = (pp >> 1) * 4 + (pp & 1);
                    const int ntB = ntA + 2;
                    const int cA = bcol + wn * 64 + ntA * 8 + tg * 2;
                    const int cq = cA - which * HDH;
                    const int hh = cq / DH_;
                    const int dA = cq - hh * DH_;
                    const int jA = dA & 31;
                    const int chunk = dA >> 5;
                    const float a0 = acc[mt][ntA][i0], a1 = acc[mt][ntA][i0 + 1];
                    const float b0 = acc[mt][ntB][i0], b1 = acc[mt][ntB][i0 + 1];
                    float oA0, oA1, oB0, oB1;
                    if (which == 2) {
                        oA0 = a0; oA1 = a1; oB0 = b0; oB1 = b1;
                    } else {
                        const float2* csp = g_cs + (size_t)(chunk * N_ + n) * 32;
                        const float2 cA0 = csp[jA],      cA1 = csp[jA + 1];
                        const float2 cB0 = csp[jA + 16], cB1 = csp[jA + 17];
                        oA0 = a0 * cA0.x - b0 * cA0.y;
                        oA1 = a1 * cA1.x - b1 * cA1.y;
                        oB0 = b0 * cB0.x + a0 * cB0.y;
                        oB1 = b1 * cB1.x + a1 * cB1.y;
                        if (which == 0) {
                            oA0 *= SCALE_; oA1 *= SCALE_; oB0 *= SCALE_; oB1 *= SCALE_;
                        }
                    }
                    const size_t oA = ((size_t)((bb * H_ + hh) * N_ + n)) * DH_ + dA;
                    const size_t oB = oA + 16;
                    __half* dst = (which == 0) ? g_qh : ((which == 1) ? g_kk : g_vv);
                    *(__half2*)(dst + oA) = __floats2half2_rn(oA0, oA1);
                    *(__half2*)(dst + oB) = __floats2half2_rn(oB0, oB1);
                }
            }
        }
    } else {
#pragma unroll
        for (int mt = 0; mt < 2; mt++) {
            const int r0 = brow + wm * 32 + mt * 16 + g;
#pragma unroll
            for (int nt = 0; nt < 8; nt++) {
                const int c = bcol + wn * 64 + nt * 8 + tg * 2;
                float2 v0 = make_float2(acc[mt][nt][0], acc[mt][nt][1]);
                float2 v1 = make_float2(acc[mt][nt][2], acc[mt][nt][3]);
                const float b0 = bias[c], b1 = bias[c + 1];
                v0.x += b0; v0.y += b1; v1.x += b0; v1.y += b1;
                *(float2*)(C + (size_t)r0 * N + c)       = v0;
                *(float2*)(C + (size_t)(r0 + 8) * N + c) = v1;
            }
        }
    }
}

// ---------------- fp32 -> fp16 ------------------------------------
__global__ void cvt_f16(const float* __restrict__ src, __half* __restrict__ dst, int n4) {
    const int i = blockIdx.x * blockDim.x + threadIdx.x;
    if (i >= n4) return;
    const float4 v = ((const float4*)src)[i];
    ((__half2*)dst)[i * 2]     = __floats2half2_rn(v.x, v.y);
    ((__half2*)dst)[i * 2 + 1] = __floats2half2_rn(v.z, v.w);
}

// W [K,N] -> W^T [N,K] single fp16
__global__ void transpose_f16(const float* __restrict__ W,
                              __half* __restrict__ Wt, int K, int N) {
    __shared__ float t[32][33];
    const int n0 = blockIdx.x * 32, k0 = blockIdx.y * 32;
    const int tx = threadIdx.x;
    for (int y = threadIdx.y; y < 32; y += 8)
        t[y][tx] = W[(size_t)(k0 + y) * N + n0 + tx];
    __syncthreads();
    for (int y = threadIdx.y; y < 32; y += 8)
        Wt[(size_t)(n0 + y) * K + k0 + tx] = __float2half(t[tx][y]);
}

// ---------------- Flash attention (fp16 mma.sync) -----------------
// Q, K, V, P all single fp16. Writes ctx single fp16. 2 CTAs/SM.
#define FBM    128
#define FBN    64
#define FSTRIDE 208
#define FTILE  (64 * FSTRIDE)
#define FSTAGE (2 * FTILE)
#define FLASH_SMEM (2 * FSTAGE)

__global__ void __launch_bounds__(256, 2) flash_mma() {
    extern __shared__ char sm_[];
    const uint32_t sb = smem_u32(sm_);
    const int tid = threadIdx.x;
    const int wid = tid >> 5, lane = tid & 31;
    const int g = lane >> 2, tg = lane & 3;
    const int bh = blockIdx.y;
    const int b  = bh >> 4, h = bh & 15;
    const int m0 = blockIdx.x * FBM;

    const size_t tbase = (size_t)bh * N_ * DH_;

    const int qrow = m0 + wid * 16 + g;
    const char* qh = (const char*)(g_qh + tbase + (size_t)qrow * DH_);
    uint32_t qa[6][4];
#pragma unroll
    for (int j = 0; j < 6; j++) {
        const int c0 = (j * 16 + tg * 2) * 2;
        qa[j][0] = *(const uint32_t*)(qh + c0);
        qa[j][1] = *(const uint32_t*)(qh + 8 * DH_ * 2 + c0);
        qa[j][2] = *(const uint32_t*)(qh + c0 + 16);
        qa[j][3] = *(const uint32_t*)(qh + 8 * DH_ * 2 + c0 + 16);
    }

    float oacc[12][4];
#pragma unroll
    for (int ot = 0; ot < 12; ot++)
#pragma unroll
        for (int i = 0; i < 4; i++) oacc[ot][i] = 0.f;
    float mrow0 = -1e30f, mrow1 = -1e30f, lrow0 = 0.f, lrow1 = 0.f;

    const char* srcK = (const char*)(g_kk + tbase);
    const char* srcV = (const char*)(g_vv + tbase);

    auto load_stage = [&](int s) {
        const uint32_t base = sb + (uint32_t)(s & 1) * FSTAGE;
        const int n0 = s * FBN;
#pragma unroll
        for (int i = 0; i < 6; i++) {
            const int idx = tid + i * 256;
            const int tile = idx / 768;
            const int w = idx % 768;
            const int r = w / 12, c = w % 12;
            const uint32_t so = base + (uint32_t)tile * FTILE +
                                (uint32_t)r * FSTRIDE + (uint32_t)c * 16;
            const size_t go = ((size_t)(n0 + r) * DH_ + c * 8) * 2;
            CP_ASYNC16(so, (tile == 0 ? srcK : srcV) + go);
        }
    };

    load_stage(0); CP_COMMIT();

    const int nkv = N_ / FBN;
    for (int s = 0; s < nkv; s++) {
        if (s + 1 < nkv) { load_stage(s + 1); CP_COMMIT(); CP_WAIT(1); }
        else             { CP_WAIT(0); }
        __syncthreads();

        const uint32_t kb = sb + (uint32_t)(s & 1) * FSTAGE;
        const uint32_t vb = kb + FTILE;

        float sacc[8][4];
#pragma unroll
        for (int nt = 0; nt < 8; nt++)
#pragma unroll
            for (int i = 0; i < 4; i++) sacc[nt][i] = 0.f;

#pragma unroll
        for (int j = 0; j < 6; j++) {
            uint32_t bf[8][2];
#pragma unroll
            for (int np = 0; np < 4; np++) {
                const int sel = lane >> 3;
                const uint32_t row = (uint32_t)(np * 16 + ((sel & 2) ? 8 : 0) + (lane & 7));
                const uint32_t col = (uint32_t)(j * 16 + ((sel & 1) ? 8 : 0));
                const uint32_t ad = kb + row * FSTRIDE + col * 2;
                LDMX4(bf[2*np][0], bf[2*np][1], bf[2*np+1][0], bf[2*np+1][1], ad);
            }
#pragma unroll
            for (int nt = 0; nt < 8; nt++)
                mma_f16(sacc[nt], qa[j], bf[nt]);
        }

        float mx0 = -1e30f, mx1 = -1e30f;
#pragma unroll
        for (int nt = 0; nt < 8; nt++) {
            mx0 = fmaxf(mx0, fmaxf(sacc[nt][0], sacc[nt][1]));
            mx1 = fmaxf(mx1, fmaxf(sacc[nt][2], sacc[nt][3]));
        }
        mx0 = fmaxf(mx0, __shfl_xor_sync(0xffffffffu, mx0, 1));
        mx0 = fmaxf(mx0, __shfl_xor_sync(0xffffffffu, mx0, 2));
        mx1 = fmaxf(mx1, __shfl_xor_sync(0xffffffffu, mx1, 1));
        mx1 = fmaxf(mx1, __shfl_xor_sync(0xffffffffu, mx1, 2));

        const float mn0 = fmaxf(mrow0, mx0), mn1 = fmaxf(mrow1, mx1);
        const float corr0 = __expf(mrow0 - mn0), corr1 = __expf(mrow1 - mn1);
        mrow0 = mn0; mrow1 = mn1;

        float sum0 = 0.f, sum1 = 0.f;
#pragma unroll
        for (int nt = 0; nt < 8; nt++) {
            sacc[nt][0] = __expf(sacc[nt][0] - mn0);
            sacc[nt][1] = __expf(sacc[nt][1] - mn0);
            sacc[nt][2] = __expf(sacc[nt][2] - mn1);
            sacc[nt][3] = __expf(sacc[nt][3] - mn1);
            sum0 += sacc[nt][0] + sacc[nt][1];
            sum1 += sacc[nt][2] + sacc[nt][3];
        }
        lrow0 = lrow0 * corr0 + sum0;
        lrow1 = lrow1 * corr1 + sum1;
#pragma unroll
        for (int ot = 0; ot < 12; ot++) {
            oacc[ot][0] *= corr0; oacc[ot][1] *= corr0;
            oacc[ot][2] *= corr1; oacc[ot][3] *= corr1;
        }

        // ---- O += P V (P single fp16) ----
#pragma unroll
        for (int jj = 0; jj < 4; jj++) {
            uint32_t pa[4];
            pa[0] = pk_h2(sacc[2*jj][0],   sacc[2*jj][1]);
            pa[1] = pk_h2(sacc[2*jj][2],   sacc[2*jj][3]);
            pa[2] = pk_h2(sacc[2*jj+1][0], sacc[2*jj+1][1]);
            pa[3] = pk_h2(sacc[2*jj+1][2], sacc[2*jj+1][3]);
#pragma unroll
            for (int np = 0; np < 6; np++) {
                uint32_t vf[2][2];
                const int sel = lane >> 3;
                const uint32_t row = (uint32_t)(jj * 16 + ((sel & 1) ? 8 : 0) + (lane & 7));
                const uint32_t col = (uint32_t)(np * 16 + ((sel & 2) ? 8 : 0));
                const uint32_t ad = vb + row * FSTRIDE + col * 2;
                LDMX4T(vf[0][0], vf[0][1], vf[1][0], vf[1][1], ad);
                mma_f16(oacc[2*np],   pa, vf[0]);
                mma_f16(oacc[2*np+1], pa, vf[1]);
            }
        }
        __syncthreads();
    }

    lrow0 += __shfl_xor_sync(0xffffffffu, lrow0, 1);
    lrow0 += __shfl_xor_sync(0xffffffffu, lrow0, 2);
    lrow1 += __shfl_xor_sync(0xffffffffu, lrow1, 1);
    lrow1 += __shfl_xor_sync(0xffffffffu, lrow1, 2);
    const float inv0 = 1.f / lrow0, inv1 = 1.f / lrow1;

    const int nrow = m0 + wid * 16 + g;
    const size_t ob0 = (size_t)(b * N_ + nrow) * HDH + h * DH_;
    const size_t ob1 = (size_t)(b * N_ + nrow + 8) * HDH + h * DH_;
#pragma unroll
    for (int ot = 0; ot < 12; ot++) {
        const int d0 = ot * 8 + tg * 2;
        *(__half2*)(g_chi + ob0 + d0) =
            __floats2half2_rn(oacc[ot][0] * inv0, oacc[ot][1] * inv0);
        *(__half2*)(g_chi + ob1 + d0) =
            __floats2half2_rn(oacc[ot][2] * inv1, oacc[ot][3] * inv1);
    }
}

// ------------------------------------------------------------------
extern "C" void kernel_launch(void* const* d_in, const int* in_sizes, int n_in,
                              void* d_out, int out_size) {
    const float* x    = (const float*)d_in[0];
    const float* f1   = (const float*)d_in[1];
    const float* f2   = (const float*)d_in[2];
    const float* f3   = (const float*)d_in[3];
    const float* Wqkv = (const float*)d_in[4];
    const float* Wout = (const float*)d_in[5];
    const float* bout = (const float*)d_in[6];
    float* out = (float*)d_out;

    __half *xh, *chi, *wqt, *wot;
    cudaGetSymbolAddress((void**)&xh,  g_xh);
    cudaGetSymbolAddress((void**)&chi, g_chi);
    cudaGetSymbolAddress((void**)&wqt, g_wqt);
    cudaGetSymbolAddress((void**)&wot, g_wot);

    cudaFuncSetAttribute((const void*)gemm_mma<1>,
                         cudaFuncAttributeMaxDynamicSharedMemorySize, GEMM_SMEM);
    cudaFuncSetAttribute((const void*)gemm_mma<0>,
                         cudaFuncAttributeMaxDynamicSharedMemorySize, GEMM_SMEM);
    cudaFuncSetAttribute((const void*)flash_mma,
                         cudaFuncAttributeMaxDynamicSharedMemorySize, FLASH_SMEM);

    // 0) cos/sin table
    cs_init<<<(3 * N_ * 32 + 255) / 256, 256>>>(f1, f2, f3);

    // 1) x -> fp16; weights -> transposed fp16
    cvt_f16<<<(M_ * DIM_ / 4 + 255) / 256, 256>>>(x, xh, M_ * DIM_ / 4);
    transpose_f16<<<dim3(QKV3 / 32, DIM_ / 32), dim3(32, 8)>>>(Wqkv, wqt, DIM_, QKV3);
    transpose_f16<<<dim3(HDH / 32, HDH / 32), dim3(32, 8)>>>(Wout, wot, HDH, HDH);

    // 2) QKV GEMM with fused RoPE + head-transpose epilogue
    gemm_mma<1><<<dim3(QKV3 / 128, M_ / 128), 256, GEMM_SMEM>>>(
        xh, wqt, nullptr, nullptr, QKV3, DIM_);

    // 3) Flash attention (writes ctx single fp16)
    flash_mma<<<dim3(N_ / FBM, B_ * H_), 256, FLASH_SMEM>>>();

    // 4) Output GEMM + bias
    gemm_mma<0><<<dim3(HDH / 128, M_ / 128), 256, GEMM_SMEM>>>(
        chi, wot, bout, out, HDH, HDH);
}